// round 3
// baseline (speedup 1.0000x reference)
#include <cuda_runtime.h>
#include <math.h>
#include <stdint.h>

#define BB 2
#define NN 2048
#define DIM 1024
#define HEADS 16
#define DH 64
#define RD 128
#define NT (BB*NN)

// ---------------- scratch (static device globals; no allocation) ------------
__device__ float g_qx[(size_t)NT*DIM];       // x @ Wq_x^T
__device__ float g_qa[(size_t)NT*DIM];       // a @ Wq_a^T
__device__ float g_kvx[(size_t)NT*2*DH];     // x @ Wkv_x^T
__device__ float g_kva[(size_t)NT*2*DH];     // a @ Wkv_a^T
__device__ float g_Q[(size_t)BB*HEADS*NN*RD];// (b,h,n,128), pre-scaled by 1/sqrt(128)
__device__ float g_K[(size_t)NT*RD];         // (b,n,128)
__device__ float g_V[(size_t)NT*RD];         // (b,n,128)
__device__ float g_cos[NN*DH];
__device__ float g_sin[NN*DH];

// ---------------- RoPE table (match reference fp32 angle exactly) ----------
__global__ void rope_table_kernel() {
    int i = blockIdx.x * blockDim.x + threadIdx.x;
    if (i >= NN * DH) return;
    int n = i >> 6, j = i & 63;
    // inv_freq = 10000^(-j/64) computed in double, rounded to float (matches fp32 pow to ~1ulp)
    float invf = (float)pow(10000.0, -(double)j / 64.0);
    float ang = (float)n * invf;              // fp32 multiply, exactly as the reference
    g_cos[i] = (float)cos((double)ang);       // accurate trig of the fp32 angle
    g_sin[i] = (float)sin((double)ang);
}

// ---------------- generic tiled GEMM: Y[M,Nout] = X[M,K] @ W[Nout,K]^T -----
#define GBM 64
#define GBN 64
#define GBK 16
__global__ void gemm_xwT_kernel(const float* __restrict__ X,
                                const float* __restrict__ W,
                                float* __restrict__ Y,
                                int M, int Nout, int K) {
    __shared__ float As[GBK][GBM + 1];
    __shared__ float Bs[GBK][GBN + 1];
    int tid = threadIdx.x;
    int tx = tid & 15, ty = tid >> 4;
    int m0 = blockIdx.y * GBM, n0 = blockIdx.x * GBN;

    float acc[4][4] = {};
    int idx = tid * 4;
    int lr = idx >> 4;        // row within tile (0..63)
    int lk = idx & 15;        // k within tile (0,4,8,12)

    for (int k0 = 0; k0 < K; k0 += GBK) {
        float4 va = *reinterpret_cast<const float4*>(&X[(size_t)(m0 + lr) * K + k0 + lk]);
        float4 vb = *reinterpret_cast<const float4*>(&W[(size_t)(n0 + lr) * K + k0 + lk]);
        As[lk + 0][lr] = va.x; As[lk + 1][lr] = va.y; As[lk + 2][lr] = va.z; As[lk + 3][lr] = va.w;
        Bs[lk + 0][lr] = vb.x; Bs[lk + 1][lr] = vb.y; Bs[lk + 2][lr] = vb.z; Bs[lk + 3][lr] = vb.w;
        __syncthreads();
        #pragma unroll
        for (int kk = 0; kk < GBK; kk++) {
            float a[4], b[4];
            #pragma unroll
            for (int i = 0; i < 4; i++) a[i] = As[kk][ty * 4 + i];
            #pragma unroll
            for (int j = 0; j < 4; j++) b[j] = Bs[kk][tx * 4 + j];
            #pragma unroll
            for (int i = 0; i < 4; i++)
                #pragma unroll
                for (int j = 0; j < 4; j++)
                    acc[i][j] = fmaf(a[i], b[j], acc[i][j]);
        }
        __syncthreads();
    }
    #pragma unroll
    for (int i = 0; i < 4; i++) {
        float* py = &Y[(size_t)(m0 + ty * 4 + i) * Nout + n0 + tx * 4];
        #pragma unroll
        for (int j = 0; j < 4; j++) py[j] = acc[i][j];
    }
}

// ---------------- prep: l2norm + scale + concat + rotary -------------------
// 18 warps: warps 0..15 -> Q heads, warp 16 -> K, warp 17 -> V. One block per token.
__global__ void prep_kernel(const float* __restrict__ qx_scale,
                            const float* __restrict__ qa_scale,
                            const float* __restrict__ kx_scale,
                            const float* __restrict__ ka_scale) {
    int t = blockIdx.x;                 // global token 0..4095
    int b = t >> 11, n = t & (NN - 1);
    int w = threadIdx.x >> 5, l = threadIdx.x & 31;

    float c0 = g_cos[n * DH + l],      s0 = g_sin[n * DH + l];
    float c1 = g_cos[n * DH + l + 32], s1 = g_sin[n * DH + l + 32];
    const float SC = 0.08838834764831845f; // 1/sqrt(128)

    if (w < HEADS) {
        int h = w;
        const float* px = &g_qx[(size_t)t * DIM + h * DH];
        float x0 = px[l], x1 = px[l + 32];
        float sx = x0 * x0 + x1 * x1;
        #pragma unroll
        for (int o = 16; o; o >>= 1) sx += __shfl_xor_sync(0xFFFFFFFFu, sx, o);
        float rnx = 1.0f / fmaxf(sqrtf(sx), 1e-12f);
        float qx0 = x0 * rnx * qx_scale[h * DH + l];
        float qx1 = x1 * rnx * qx_scale[h * DH + l + 32];

        const float* pa = &g_qa[(size_t)t * DIM + h * DH];
        float a0 = pa[l], a1 = pa[l + 32];
        float sa = a0 * a0 + a1 * a1;
        #pragma unroll
        for (int o = 16; o; o >>= 1) sa += __shfl_xor_sync(0xFFFFFFFFu, sa, o);
        float rna = 1.0f / fmaxf(sqrtf(sa), 1e-12f);
        float qa0 = a0 * rna * qa_scale[h * DH + l];
        float qa1 = a1 * rna * qa_scale[h * DH + l + 32];

        float* pq = &g_Q[(((size_t)b * HEADS + h) * NN + n) * RD];
        pq[l]      = SC * (qx0 * c0 - qa0 * s0);
        pq[l + 64] = SC * (qa0 * c0 + qx0 * s0);
        pq[l + 32] = SC * (qx1 * c1 - qa1 * s1);
        pq[l + 96] = SC * (qa1 * c1 + qx1 * s1);
    } else if (w == 16) {   // K
        const float* px = &g_kvx[(size_t)t * 2 * DH];
        float x0 = px[l], x1 = px[l + 32];
        float sx = x0 * x0 + x1 * x1;
        #pragma unroll
        for (int o = 16; o; o >>= 1) sx += __shfl_xor_sync(0xFFFFFFFFu, sx, o);
        float rnx = 1.0f / fmaxf(sqrtf(sx), 1e-12f);
        float kx0 = x0 * rnx * kx_scale[l];
        float kx1 = x1 * rnx * kx_scale[l + 32];

        const float* pa = &g_kva[(size_t)t * 2 * DH];
        float a0 = pa[l], a1 = pa[l + 32];
        float sa = a0 * a0 + a1 * a1;
        #pragma unroll
        for (int o = 16; o; o >>= 1) sa += __shfl_xor_sync(0xFFFFFFFFu, sa, o);
        float rna = 1.0f / fmaxf(sqrtf(sa), 1e-12f);
        float ka0 = a0 * rna * ka_scale[l];
        float ka1 = a1 * rna * ka_scale[l + 32];

        float* pk = &g_K[(size_t)t * RD];
        pk[l]      = kx0 * c0 - ka0 * s0;
        pk[l + 64] = ka0 * c0 + kx0 * s0;
        pk[l + 32] = kx1 * c1 - ka1 * s1;
        pk[l + 96] = ka1 * c1 + kx1 * s1;
    } else {                // V (no norm, no rotary)
        const float* px = &g_kvx[(size_t)t * 2 * DH + DH];
        const float* pa = &g_kva[(size_t)t * 2 * DH + DH];
        float* pv = &g_V[(size_t)t * RD];
        pv[l]      = px[l];
        pv[l + 32] = px[l + 32];
        pv[l + 64] = pa[l];
        pv[l + 96] = pa[l + 32];
    }
}

// ---------------- flash attention (fp32, online softmax) -------------------
// grid: (32 q-tiles, 16 heads, 2 batches); block 256 threads.
// smem: sQt[128][65] | sKt[128][65] | sV[64][132] | sS[64][65] | sM,sL,sA[64]
#define SQT_OFF 0
#define SKT_OFF (128*65)
#define SV_OFF  (SKT_OFF + 128*65)
#define SS_OFF  (SV_OFF + 64*132)
#define SM_OFF  (SS_OFF + 64*65)
#define SL_OFF  (SM_OFF + 64)
#define SA_OFF  (SL_OFF + 64)
#define ATTN_SMEM_FLOATS (SA_OFF + 64)

__global__ void attn_kernel(float* __restrict__ out) {
    extern __shared__ float sm[];
    float* sQt = sm + SQT_OFF;
    float* sKt = sm + SKT_OFF;
    float* sV  = sm + SV_OFF;
    float* sS  = sm + SS_OFF;
    float* sM  = sm + SM_OFF;
    float* sL  = sm + SL_OFF;
    float* sA  = sm + SA_OFF;

    int qt = blockIdx.x, h = blockIdx.y, b = blockIdx.z;
    int tid = threadIdx.x;
    int tx = tid & 15, ty = tid >> 4;

    // load Q tile transposed: sQt[d][q]
    const float* Qg = &g_Q[(((size_t)b * HEADS + h) * NN + (size_t)qt * 64) * RD];
    for (int i = tid; i < 64 * RD; i += 256) {
        int q = i >> 7, d = i & 127;
        sQt[d * 65 + q] = Qg[i];
    }
    if (tid < 64) { sM[tid] = -INFINITY; sL[tid] = 0.0f; }

    float accO[4][8] = {};
    const float* Kg = &g_K[(size_t)b * NN * RD];
    const float* Vg = &g_V[(size_t)b * NN * RD];

    for (int kt = 0; kt < NN / 64; kt++) {
        __syncthreads();   // previous PV done (and Q/state init on first iter)
        const float* Kt = Kg + (size_t)kt * 64 * RD;
        const float* Vt = Vg + (size_t)kt * 64 * RD;
        for (int i = tid; i < 64 * RD; i += 256) {
            int r = i >> 7, d = i & 127;
            sKt[d * 65 + r] = Kt[i];
            sV[r * 132 + d] = Vt[i];
        }
        __syncthreads();

        // S = Q K^T (4q x 4k per thread)
        float s[4][4] = {};
        #pragma unroll 4
        for (int d = 0; d < RD; d++) {
            float a[4], bk[4];
            #pragma unroll
            for (int i = 0; i < 4; i++) a[i] = sQt[d * 65 + ty * 4 + i];
            #pragma unroll
            for (int j = 0; j < 4; j++) bk[j] = sKt[d * 65 + tx * 4 + j];
            #pragma unroll
            for (int i = 0; i < 4; i++)
                #pragma unroll
                for (int j = 0; j < 4; j++)
                    s[i][j] = fmaf(a[i], bk[j], s[i][j]);
        }
        #pragma unroll
        for (int i = 0; i < 4; i++)
            #pragma unroll
            for (int j = 0; j < 4; j++)
                sS[(ty * 4 + i) * 65 + tx * 4 + j] = s[i][j];
        __syncthreads();

        // online softmax: 4 threads per row, 16 cols each
        {
            int r = tid >> 2, cb = (tid & 3) * 16;
            float vals[16];
            float mloc = -INFINITY;
            #pragma unroll
            for (int c = 0; c < 16; c++) {
                vals[c] = sS[r * 65 + cb + c];
                mloc = fmaxf(mloc, vals[c]);
            }
            mloc = fmaxf(mloc, __shfl_xor_sync(0xFFFFFFFFu, mloc, 1));
            mloc = fmaxf(mloc, __shfl_xor_sync(0xFFFFFFFFu, mloc, 2));
            float mold = sM[r];
            float mnew = fmaxf(mold, mloc);
            float lsum = 0.0f;
            #pragma unroll
            for (int c = 0; c < 16; c++) {
                float p = __expf(vals[c] - mnew);
                sS[r * 65 + cb + c] = p;
                lsum += p;
            }
            lsum += __shfl_xor_sync(0xFFFFFFFFu, lsum, 1);
            lsum += __shfl_xor_sync(0xFFFFFFFFu, lsum, 2);
            if ((tid & 3) == 0) {
                float alpha = __expf(mold - mnew);   // exp(-inf)=0 on first tile
                sA[r] = alpha;
                sM[r] = mnew;
                sL[r] = sL[r] * alpha + lsum;
            }
        }
        __syncthreads();

        // O = O*alpha + P V   (4q x 8d per thread)
        float al[4];
        #pragma unroll
        for (int i = 0; i < 4; i++) al[i] = sA[ty * 4 + i];
        #pragma unroll
        for (int i = 0; i < 4; i++)
            #pragma unroll
            for (int j = 0; j < 8; j++)
                accO[i][j] *= al[i];

        #pragma unroll 2
        for (int k = 0; k < 64; k++) {
            float p[4];
            #pragma unroll
            for (int i = 0; i < 4; i++) p[i] = sS[(ty * 4 + i) * 65 + k];
            float4 v0 = *reinterpret_cast<const float4*>(&sV[k * 132 + tx * 8]);
            float4 v1 = *reinterpret_cast<const float4*>(&sV[k * 132 + tx * 8 + 4]);
            float v[8] = {v0.x, v0.y, v0.z, v0.w, v1.x, v1.y, v1.z, v1.w};
            #pragma unroll
            for (int i = 0; i < 4; i++)
                #pragma unroll
                for (int j = 0; j < 8; j++)
                    accO[i][j] = fmaf(p[i], v[j], accO[i][j]);
        }
    }
    __syncthreads();

    // normalize and store: out[b][n][h*128 + d]
    #pragma unroll
    for (int i = 0; i < 4; i++) {
        float rl = 1.0f / sL[ty * 4 + i];
        int q = qt * 64 + ty * 4 + i;
        float* po = &out[((size_t)(b * NN + q)) * (HEADS * RD) + h * RD + tx * 8];
        #pragma unroll
        for (int j = 0; j < 8; j++) po[j] = accO[i][j] * rl;
    }
}

// ---------------- launch ---------------------------------------------------
extern "C" void kernel_launch(void* const* d_in, const int* in_sizes, int n_in,
                              void* d_out, int out_size) {
    const float* x        = (const float*)d_in[0];
    const float* a        = (const float*)d_in[1];
    const float* Wq_x     = (const float*)d_in[2];
    const float* Wkv_x    = (const float*)d_in[3];
    const float* Wq_a     = (const float*)d_in[4];
    const float* Wkv_a    = (const float*)d_in[5];
    const float* qx_scale = (const float*)d_in[6];
    const float* qa_scale = (const float*)d_in[7];
    const float* kx_scale = (const float*)d_in[8];
    const float* ka_scale = (const float*)d_in[9];
    float* out = (float*)d_out;

    // scratch pointers via device symbols (resolved at compile time)
    float *p_qx, *p_qa, *p_kvx, *p_kva;
    cudaGetSymbolAddress((void**)&p_qx,  g_qx);
    cudaGetSymbolAddress((void**)&p_qa,  g_qa);
    cudaGetSymbolAddress((void**)&p_kvx, g_kvx);
    cudaGetSymbolAddress((void**)&p_kva, g_kva);

    rope_table_kernel<<<(NN * DH + 255) / 256, 256>>>();

    gemm_xwT_kernel<<<dim3(DIM / GBN, NT / GBM), 256>>>(x, Wq_x, p_qx, NT, DIM, DIM);
    gemm_xwT_kernel<<<dim3(DIM / GBN, NT / GBM), 256>>>(a, Wq_a, p_qa, NT, DIM, DIM);
    gemm_xwT_kernel<<<dim3(2 * DH / GBN, NT / GBM), 256>>>(x, Wkv_x, p_kvx, NT, 2 * DH, DIM);
    gemm_xwT_kernel<<<dim3(2 * DH / GBN, NT / GBM), 256>>>(a, Wkv_a, p_kva, NT, 2 * DH, DIM);

    prep_kernel<<<NT, 18 * 32>>>(qx_scale, qa_scale, kx_scale, ka_scale);

    int smem_bytes = ATTN_SMEM_FLOATS * (int)sizeof(float);
    cudaFuncSetAttribute(attn_kernel, cudaFuncAttributeMaxDynamicSharedMemorySize, smem_bytes);
    attn_kernel<<<dim3(NN / 64, HEADS, BB), 256, smem_bytes>>>(out);
}

// round 5
// speedup vs baseline: 3.0841x; 3.0841x over previous
#include <cuda_runtime.h>
#include <cuda_fp16.h>
#include <math.h>
#include <stdint.h>

#define BB 2
#define NN 2048
#define DIM 1024
#define HEADS 16
#define DH 64
#define RD 128
#define NT (BB*NN)

// ---------------- scratch (static device globals; no allocation) ------------
__device__ float g_qx[(size_t)NT*DIM];       // x @ Wq_x^T
__device__ float g_qa[(size_t)NT*DIM];       // a @ Wq_a^T
__device__ float g_kvx[(size_t)NT*2*DH];     // x @ Wkv_x^T
__device__ float g_kva[(size_t)NT*2*DH];     // a @ Wkv_a^T
__device__ __half g_Qh[(size_t)BB*HEADS*NN*RD]; // (b,h,n,128), pre-scaled 1/sqrt(128)
__device__ __half g_Kh[(size_t)NT*RD];          // (b,n,128)
__device__ __half g_Vh[(size_t)NT*RD];          // (b,n,128)
__device__ float g_cos[NN*DH];
__device__ float g_sin[NN*DH];

// ---------------- RoPE table (match reference fp32 angle exactly) ----------
__global__ void rope_table_kernel() {
    int i = blockIdx.x * blockDim.x + threadIdx.x;
    if (i >= NN * DH) return;
    int n = i >> 6, j = i & 63;
    float invf = (float)pow(10000.0, -(double)j / 64.0);
    float ang = (float)n * invf;              // fp32 multiply, as the reference
    g_cos[i] = (float)cos((double)ang);       // accurate trig of the fp32 angle
    g_sin[i] = (float)sin((double)ang);
}

// ---------------- generic tiled GEMM: Y[M,Nout] = X[M,K] @ W[Nout,K]^T -----
#define GBM 64
#define GBN 64
#define GBK 16
__global__ void gemm_xwT_kernel(const float* __restrict__ X,
                                const float* __restrict__ W,
                                float* __restrict__ Y,
                                int M, int Nout, int K) {
    __shared__ float As[GBK][GBM + 1];
    __shared__ float Bs[GBK][GBN + 1];
    int tid = threadIdx.x;
    int tx = tid & 15, ty = tid >> 4;
    int m0 = blockIdx.y * GBM, n0 = blockIdx.x * GBN;

    float acc[4][4] = {};
    int idx = tid * 4;
    int lr = idx >> 4;        // row within tile (0..63)
    int lk = idx & 15;        // k within tile (0,4,8,12)

    for (int k0 = 0; k0 < K; k0 += GBK) {
        float4 va = *reinterpret_cast<const float4*>(&X[(size_t)(m0 + lr) * K + k0 + lk]);
        float4 vb = *reinterpret_cast<const float4*>(&W[(size_t)(n0 + lr) * K + k0 + lk]);
        As[lk + 0][lr] = va.x; As[lk + 1][lr] = va.y; As[lk + 2][lr] = va.z; As[lk + 3][lr] = va.w;
        Bs[lk + 0][lr] = vb.x; Bs[lk + 1][lr] = vb.y; Bs[lk + 2][lr] = vb.z; Bs[lk + 3][lr] = vb.w;
        __syncthreads();
        #pragma unroll
        for (int kk = 0; kk < GBK; kk++) {
            float a[4], b[4];
            #pragma unroll
            for (int i = 0; i < 4; i++) a[i] = As[kk][ty * 4 + i];
            #pragma unroll
            for (int j = 0; j < 4; j++) b[j] = Bs[kk][tx * 4 + j];
            #pragma unroll
            for (int i = 0; i < 4; i++)
                #pragma unroll
                for (int j = 0; j < 4; j++)
                    acc[i][j] = fmaf(a[i], b[j], acc[i][j]);
        }
        __syncthreads();
    }
    #pragma unroll
    for (int i = 0; i < 4; i++) {
        float* py = &Y[(size_t)(m0 + ty * 4 + i) * Nout + n0 + tx * 4];
        #pragma unroll
        for (int j = 0; j < 4; j++) py[j] = acc[i][j];
    }
}

// ---------------- prep: l2norm + scale + concat + rotary -> fp16 -----------
__global__ void prep_kernel(const float* __restrict__ qx_scale,
                            const float* __restrict__ qa_scale,
                            const float* __restrict__ kx_scale,
                            const float* __restrict__ ka_scale) {
    int t = blockIdx.x;                 // global token 0..4095
    int b = t >> 11, n = t & (NN - 1);
    int w = threadIdx.x >> 5, l = threadIdx.x & 31;

    float c0 = g_cos[n * DH + l],      s0 = g_sin[n * DH + l];
    float c1 = g_cos[n * DH + l + 32], s1 = g_sin[n * DH + l + 32];
    const float SC = 0.08838834764831845f; // 1/sqrt(128)

    if (w < HEADS) {
        int h = w;
        const float* px = &g_qx[(size_t)t * DIM + h * DH];
        float x0 = px[l], x1 = px[l + 32];
        float sx = x0 * x0 + x1 * x1;
        #pragma unroll
        for (int o = 16; o; o >>= 1) sx += __shfl_xor_sync(0xFFFFFFFFu, sx, o);
        float rnx = 1.0f / fmaxf(sqrtf(sx), 1e-12f);
        float qx0 = x0 * rnx * qx_scale[h * DH + l];
        float qx1 = x1 * rnx * qx_scale[h * DH + l + 32];

        const float* pa = &g_qa[(size_t)t * DIM + h * DH];
        float a0 = pa[l], a1 = pa[l + 32];
        float sa = a0 * a0 + a1 * a1;
        #pragma unroll
        for (int o = 16; o; o >>= 1) sa += __shfl_xor_sync(0xFFFFFFFFu, sa, o);
        float rna = 1.0f / fmaxf(sqrtf(sa), 1e-12f);
        float qa0 = a0 * rna * qa_scale[h * DH + l];
        float qa1 = a1 * rna * qa_scale[h * DH + l + 32];

        __half* pq = &g_Qh[(((size_t)b * HEADS + h) * NN + n) * RD];
        pq[l]      = __float2half_rn(SC * (qx0 * c0 - qa0 * s0));
        pq[l + 64] = __float2half_rn(SC * (qa0 * c0 + qx0 * s0));
        pq[l + 32] = __float2half_rn(SC * (qx1 * c1 - qa1 * s1));
        pq[l + 96] = __float2half_rn(SC * (qa1 * c1 + qx1 * s1));
    } else if (w == 16) {   // K
        const float* px = &g_kvx[(size_t)t * 2 * DH];
        float x0 = px[l], x1 = px[l + 32];
        float sx = x0 * x0 + x1 * x1;
        #pragma unroll
        for (int o = 16; o; o >>= 1) sx += __shfl_xor_sync(0xFFFFFFFFu, sx, o);
        float rnx = 1.0f / fmaxf(sqrtf(sx), 1e-12f);
        float kx0 = x0 * rnx * kx_scale[l];
        float kx1 = x1 * rnx * kx_scale[l + 32];

        const float* pa = &g_kva[(size_t)t * 2 * DH];
        float a0 = pa[l], a1 = pa[l + 32];
        float sa = a0 * a0 + a1 * a1;
        #pragma unroll
        for (int o = 16; o; o >>= 1) sa += __shfl_xor_sync(0xFFFFFFFFu, sa, o);
        float rna = 1.0f / fmaxf(sqrtf(sa), 1e-12f);
        float ka0 = a0 * rna * ka_scale[l];
        float ka1 = a1 * rna * ka_scale[l + 32];

        __half* pk = &g_Kh[(size_t)t * RD];
        pk[l]      = __float2half_rn(kx0 * c0 - ka0 * s0);
        pk[l + 64] = __float2half_rn(ka0 * c0 + kx0 * s0);
        pk[l + 32] = __float2half_rn(kx1 * c1 - ka1 * s1);
        pk[l + 96] = __float2half_rn(ka1 * c1 + kx1 * s1);
    } else {                // V (no norm, no rotary)
        const float* px = &g_kvx[(size_t)t * 2 * DH + DH];
        const float* pa = &g_kva[(size_t)t * 2 * DH + DH];
        __half* pv = &g_Vh[(size_t)t * RD];
        pv[l]      = __float2half_rn(px[l]);
        pv[l + 32] = __float2half_rn(px[l + 32]);
        pv[l + 64] = __float2half_rn(pa[l]);
        pv[l + 96] = __float2half_rn(pa[l + 32]);
    }
}

// ---------------- tensor-core flash attention (fp16 mma, fp32 softmax) -----
// Block: 256 thr = 8 warps; 128 queries per block (16 rows per warp).
// Key tiles of 64. smem: K[64][136] fp16 | V[64][136] fp16 (Q staging aliases both).
#define PADW 136

#define LDSM4(R0,R1,R2,R3,ADDR) \
    asm volatile("ldmatrix.sync.aligned.m8n8.x4.shared.b16 {%0,%1,%2,%3}, [%4];" \
        : "=r"(R0),"=r"(R1),"=r"(R2),"=r"(R3) : "r"(ADDR))
#define LDSM4T(R0,R1,R2,R3,ADDR) \
    asm volatile("ldmatrix.sync.aligned.m8n8.x4.trans.shared.b16 {%0,%1,%2,%3}, [%4];" \
        : "=r"(R0),"=r"(R1),"=r"(R2),"=r"(R3) : "r"(ADDR))
#define MMA16816(C, A, B0, B1) \
    asm volatile("mma.sync.aligned.m16n8k16.row.col.f32.f16.f16.f32 " \
        "{%0,%1,%2,%3},{%4,%5,%6,%7},{%8,%9},{%0,%1,%2,%3};" \
        : "+f"((C)[0]),"+f"((C)[1]),"+f"((C)[2]),"+f"((C)[3]) \
        : "r"((A)[0]),"r"((A)[1]),"r"((A)[2]),"r"((A)[3]), "r"(B0),"r"(B1))

__device__ __forceinline__ uint32_t pack_f16(float lo, float hi) {
    __half2 p = __floats2half2_rn(lo, hi);
    return *reinterpret_cast<uint32_t*>(&p);
}

__global__ void __launch_bounds__(256) attn_mma_kernel(float* __restrict__ out) {
    extern __shared__ __half sm[];
    __half* sK = sm;               // [64][PADW]
    __half* sV = sm + 64 * PADW;   // [64][PADW]

    const int qb = blockIdx.x, h = blockIdx.y, b = blockIdx.z;
    const int tid = threadIdx.x, w = tid >> 5, lane = tid & 31;
    const int q0 = w * 16;

    // ---- stage Q tile (128x128 fp16) into smem (aliases K|V), preload a-frags
    const __half* Qg = g_Qh + (((size_t)b * HEADS + h) * NN + (size_t)qb * 128) * RD;
    for (int i = tid; i < 128 * 16; i += 256) {
        int r = i >> 4, c = i & 15;
        *reinterpret_cast<uint4*>(&sm[r * PADW + c * 8]) =
            *reinterpret_cast<const uint4*>(&Qg[r * RD + c * 8]);
    }
    __syncthreads();

    uint32_t qa[8][4];
    {
        uint32_t qbase = (uint32_t)__cvta_generic_to_shared(
            &sm[(q0 + (lane & 15)) * PADW + ((lane >> 4) << 3)]);
        #pragma unroll
        for (int ks = 0; ks < 8; ks++) {
            uint32_t addr = qbase + ks * 16 * 2;
            LDSM4(qa[ks][0], qa[ks][1], qa[ks][2], qa[ks][3], addr);
        }
    }
    __syncthreads();   // Q reads done; smem reusable for K/V

    float m_[2] = {-INFINITY, -INFINITY};
    float l_[2] = {0.0f, 0.0f};
    float o[16][4] = {};

    const __half* Kg = g_Kh + (size_t)b * NN * RD;
    const __half* Vg = g_Vh + (size_t)b * NN * RD;

    const uint32_t kbase = (uint32_t)__cvta_generic_to_shared(
        &sK[((lane & 7) + ((lane >> 4) << 3)) * PADW + (lane & 8)]);
    const uint32_t vbase = (uint32_t)__cvta_generic_to_shared(
        &sV[(lane & 15) * PADW + ((lane >> 4) << 3)]);

    for (int kt = 0; kt < NN / 64; kt++) {
        __syncthreads();   // previous iteration's reads done
        {
            const __half* Kt = Kg + (size_t)kt * 64 * RD;
            const __half* Vt = Vg + (size_t)kt * 64 * RD;
            for (int i = tid; i < 64 * 16; i += 256) {
                int r = i >> 4, c = i & 15;
                *reinterpret_cast<uint4*>(&sK[r * PADW + c * 8]) =
                    *reinterpret_cast<const uint4*>(&Kt[r * RD + c * 8]);
                *reinterpret_cast<uint4*>(&sV[r * PADW + c * 8]) =
                    *reinterpret_cast<const uint4*>(&Vt[r * RD + c * 8]);
            }
        }
        __syncthreads();

        // ---- S = Q K^T : 8 n-tiles (64 keys), per-thread c-frags s[8][4]
        float s[8][4] = {};
        #pragma unroll
        for (int ks = 0; ks < 8; ks++) {
            #pragma unroll
            for (int np = 0; np < 4; np++) {   // 16 keys per np
                uint32_t addr = kbase + (uint32_t)((np * 16 * PADW + ks * 16) * 2);
                uint32_t b0, b1, b2, b3;
                LDSM4(b0, b1, b2, b3, addr);
                MMA16816(s[2 * np],     qa[ks], b0, b1);
                MMA16816(s[2 * np + 1], qa[ks], b2, b3);
            }
        }

        // ---- online softmax in registers (rows: lane/4 and lane/4+8)
        float mnew[2], alpha[2], lsum[2];
        #pragma unroll
        for (int r = 0; r < 2; r++) {
            float mx = m_[r];
            #pragma unroll
            for (int nt = 0; nt < 8; nt++)
                mx = fmaxf(mx, fmaxf(s[nt][2 * r], s[nt][2 * r + 1]));
            mx = fmaxf(mx, __shfl_xor_sync(0xFFFFFFFFu, mx, 1));
            mx = fmaxf(mx, __shfl_xor_sync(0xFFFFFFFFu, mx, 2));
            mnew[r] = mx;
            alpha[r] = __expf(m_[r] - mx);   // exp(-inf)=0 first tile
            lsum[r] = 0.0f;
        }
        #pragma unroll
        for (int nt = 0; nt < 8; nt++) {
            #pragma unroll
            for (int e = 0; e < 4; e++) {
                int r = e >> 1;
                float p = __expf(s[nt][e] - mnew[r]);
                s[nt][e] = p;
                lsum[r] += p;
            }
        }
        #pragma unroll
        for (int r = 0; r < 2; r++) {
            lsum[r] += __shfl_xor_sync(0xFFFFFFFFu, lsum[r], 1);
            lsum[r] += __shfl_xor_sync(0xFFFFFFFFu, lsum[r], 2);
            l_[r] = l_[r] * alpha[r] + lsum[r];
            m_[r] = mnew[r];
        }
        #pragma unroll
        for (int j = 0; j < 16; j++) {
            o[j][0] *= alpha[0]; o[j][1] *= alpha[0];
            o[j][2] *= alpha[1]; o[j][3] *= alpha[1];
        }

        // ---- O += P V : pack P c-frags into fp16 a-frags, V via ldmatrix.trans
        #pragma unroll
        for (int ks2 = 0; ks2 < 4; ks2++) {   // 16 keys per step
            uint32_t pa[4];
            pa[0] = pack_f16(s[2 * ks2][0],     s[2 * ks2][1]);
            pa[1] = pack_f16(s[2 * ks2][2],     s[2 * ks2][3]);
            pa[2] = pack_f16(s[2 * ks2 + 1][0], s[2 * ks2 + 1][1]);
            pa[3] = pack_f16(s[2 * ks2 + 1][2], s[2 * ks2 + 1][3]);
            #pragma unroll
            for (int np = 0; np < 8; np++) {  // 16 d-cols per np
                uint32_t addr = vbase + (uint32_t)((ks2 * 16 * PADW + np * 16) * 2);
                uint32_t v0, v1, v2, v3;
                LDSM4T(v0, v1, v2, v3, addr);
                MMA16816(o[2 * np],     pa, v0, v1);
                MMA16816(o[2 * np + 1], pa, v2, v3);
            }
        }
    }

    // ---- normalize and store fp32: out[b][q][h*128+d]
    float rl0 = 1.0f / l_[0], rl1 = 1.0f / l_[1];
    int qrow = qb * 128 + q0 + (lane >> 2);
    #pragma unroll
    for (int j = 0; j < 16; j++) {
        int d = h * RD + j * 8 + 2 * (lane & 3);
        float* p0 = &out[((size_t)(b * NN + qrow)) * (HEADS * RD) + d];
        float* p1 = &out[((size_t)(b * NN + qrow + 8)) * (HEADS * RD) + d];
        *reinterpret_cast<float2*>(p0) = make_float2(o[j][0] * rl0, o[j][1] * rl0);
        *reinterpret_cast<float2*>(p1) = make_float2(o[j][2] * rl1, o[j][3] * rl1);
    }
}

// ---------------- launch ---------------------------------------------------
extern "C" void kernel_launch(void* const* d_in, const int* in_sizes, int n_in,
                              void* d_out, int out_size) {
    const float* x        = (const float*)d_in[0];
    const float* a        = (const float*)d_in[1];
    const float* Wq_x     = (const float*)d_in[2];
    const float* Wkv_x    = (const float*)d_in[3];
    const float* Wq_a     = (const float*)d_in[4];
    const float* Wkv_a    = (const float*)d_in[5];
    const float* qx_scale = (const float*)d_in[6];
    const float* qa_scale = (const float*)d_in[7];
    const float* kx_scale = (const float*)d_in[8];
    const float* ka_scale = (const float*)d_in[9];
    float* out = (float*)d_out;

    float *p_qx, *p_qa, *p_kvx, *p_kva;
    cudaGetSymbolAddress((void**)&p_qx,  g_qx);
    cudaGetSymbolAddress((void**)&p_qa,  g_qa);
    cudaGetSymbolAddress((void**)&p_kvx, g_kvx);
    cudaGetSymbolAddress((void**)&p_kva, g_kva);

    rope_table_kernel<<<(NN * DH + 255) / 256, 256>>>();

    gemm_xwT_kernel<<<dim3(DIM / GBN, NT / GBM), 256>>>(x, Wq_x, p_qx, NT, DIM, DIM);
    gemm_xwT_kernel<<<dim3(DIM / GBN, NT / GBM), 256>>>(a, Wq_a, p_qa, NT, DIM, DIM);
    gemm_xwT_kernel<<<dim3(2 * DH / GBN, NT / GBM), 256>>>(x, Wkv_x, p_kvx, NT, 2 * DH, DIM);
    gemm_xwT_kernel<<<dim3(2 * DH / GBN, NT / GBM), 256>>>(a, Wkv_a, p_kva, NT, 2 * DH, DIM);

    prep_kernel<<<NT, 18 * 32>>>(qx_scale, qa_scale, kx_scale, ka_scale);

    int smem_bytes = 2 * 64 * PADW * (int)sizeof(__half);  // 34816 B
    cudaFuncSetAttribute(attn_mma_kernel, cudaFuncAttributeMaxDynamicSharedMemorySize, smem_bytes);
    attn_mma_kernel<<<dim3(NN / 128, HEADS, BB), 256, smem_bytes>>>(out);
}

// round 8
// speedup vs baseline: 4.8953x; 1.5873x over previous
#include <cuda_runtime.h>
#include <cuda_fp16.h>
#include <math.h>
#include <stdint.h>

#define BB 2
#define NN 2048
#define DIM 1024
#define HEADS 16
#define DH 64
#define RD 128
#define NT (BB*NN)
#define K3 3072           // expanded K for split-precision fp16 GEMM
#define NCHUNK (K3/32)    // 96

// ---------------- scratch (static device globals; no allocation) ------------
__device__ float g_qx[(size_t)NT*DIM];       // x @ Wq_x^T
__device__ float g_qa[(size_t)NT*DIM];       // a @ Wq_a^T
__device__ float g_kvx[(size_t)NT*2*DH];     // x @ Wkv_x^T
__device__ float g_kva[(size_t)NT*2*DH];     // a @ Wkv_a^T
__device__ __half g_Qh[(size_t)BB*HEADS*NN*RD]; // (b,h,n,128), pre-scaled 1/sqrt(128)
__device__ __half g_Kh[(size_t)NT*RD];          // (b,n,128)
__device__ __half g_Vh[(size_t)NT*RD];          // (b,n,128)
__device__ float g_cos[NN*DH];
__device__ float g_sin[NN*DH];
__device__ float g_invf[DH];

// expanded split-precision operands (hi|lo|hi for X, hi|hi|lo for W)
__device__ __half g_xe[(size_t)NT*K3];
__device__ __half g_ae[(size_t)NT*K3];
__device__ __half g_wqxe[(size_t)DIM*K3];
__device__ __half g_wqae[(size_t)DIM*K3];
__device__ __half g_wkxe[(size_t)2*DH*K3];
__device__ __half g_wkae[(size_t)2*DH*K3];

// ---------------- RoPE tables ----------------------------------------------
__global__ void rope_invf_kernel() {
    int j = threadIdx.x;
    if (j < DH) g_invf[j] = (float)pow(10000.0, -(double)j / 64.0);
}

__global__ void rope_table_kernel() {
    int i = blockIdx.x * blockDim.x + threadIdx.x;
    if (i >= NN * DH) return;
    int n = i >> 6, j = i & 63;
    float ang = (float)n * g_invf[j];        // fp32 multiply, as the reference
    // two-term Cody-Waite range reduction: 2*pi = HI + LO
    const float HI = 6.28318548202514648f;
    const float LO = -1.7484556e-7f;
    float k = rintf(ang * 0.15915494309189535f);
    float r = fmaf(-k, HI, ang);
    r = fmaf(-k, LO, r);                     // r in [-pi, pi], err ~2e-7
    g_cos[i] = cosf(r);
    g_sin[i] = sinf(r);
}

// ---------------- split-precision expansion --------------------------------
// src: [rows,1024] fp32.  dst: [rows,3072] fp16.
// wmode=0 (activations): [hi | lo | hi];  wmode=1 (weights): [hi | hi | lo]
__global__ void split_expand_kernel(const float* __restrict__ src,
                                    __half* __restrict__ dst,
                                    int total, int wmode) {
    int i = blockIdx.x * blockDim.x + threadIdx.x;
    if (i >= total) return;
    int r = i >> 10, c = i & 1023;
    float v = src[i];
    __half hi = __float2half_rn(v);
    __half lo = __float2half_rn(v - __half2float(hi));
    __half* d = dst + (size_t)r * K3;
    if (wmode) { d[c] = hi; d[c + 1024] = hi; d[c + 2048] = lo; }
    else       { d[c] = hi; d[c + 1024] = lo; d[c + 2048] = hi; }
}

// ---------------- MMA helpers ----------------------------------------------
#define LDSM4(R0,R1,R2,R3,ADDR) \
    asm volatile("ldmatrix.sync.aligned.m8n8.x4.shared.b16 {%0,%1,%2,%3}, [%4];" \
        : "=r"(R0),"=r"(R1),"=r"(R2),"=r"(R3) : "r"(ADDR))
#define LDSM4T(R0,R1,R2,R3,ADDR) \
    asm volatile("ldmatrix.sync.aligned.m8n8.x4.trans.shared.b16 {%0,%1,%2,%3}, [%4];" \
        : "=r"(R0),"=r"(R1),"=r"(R2),"=r"(R3) : "r"(ADDR))
#define MMA16816(C, A, B0, B1) \
    asm volatile("mma.sync.aligned.m16n8k16.row.col.f32.f16.f16.f32 " \
        "{%0,%1,%2,%3},{%4,%5,%6,%7},{%8,%9},{%0,%1,%2,%3};" \
        : "+f"((C)[0]),"+f"((C)[1]),"+f"((C)[2]),"+f"((C)[3]) \
        : "r"((A)[0]),"r"((A)[1]),"r"((A)[2]),"r"((A)[3]), "r"(B0),"r"(B1))

// ---------------- fp16 tensor-core NT GEMM: Y[M,Nout] = A[M,K3] @ B[Nout,K3]^T
// Block: 128x128 tile, 256 threads (8 warps as 4m x 2n), K-chunks of 32,
// cp.async double-buffered.  Y fp32.
#define GP 40   // smem row pitch in halves (32 data + 8 pad)

__global__ void __launch_bounds__(256) hgemm_nt_kernel(const __half* __restrict__ A,
                                                       const __half* __restrict__ B,
                                                       float* __restrict__ Y,
                                                       int Nout) {
    __shared__ __half sA[2][128 * GP];
    __shared__ __half sB[2][128 * GP];
    const int tid = threadIdx.x, lane = tid & 31, w = tid >> 5;
    const int wm = w & 3, wn = w >> 2;
    const int bm0 = blockIdx.y * 128, bn0 = blockIdx.x * 128;

    const __half* Ag = A + (size_t)bm0 * K3;
    const __half* Bg = B + (size_t)bn0 * K3;

    auto load_chunk = [&](int buf, int k0) {
        #pragma unroll
        for (int p = 0; p < 2; p++) {
            int idx = tid + p * 256;
            int row = idx >> 2, c8 = idx & 3;
            uint32_t da = (uint32_t)__cvta_generic_to_shared(&sA[buf][row * GP + c8 * 8]);
            const __half* ga = Ag + (size_t)row * K3 + k0 + c8 * 8;
            asm volatile("cp.async.cg.shared.global [%0], [%1], 16;\n" :: "r"(da), "l"(ga));
            uint32_t db = (uint32_t)__cvta_generic_to_shared(&sB[buf][row * GP + c8 * 8]);
            const __half* gb = Bg + (size_t)row * K3 + k0 + c8 * 8;
            asm volatile("cp.async.cg.shared.global [%0], [%1], 16;\n" :: "r"(db), "l"(gb));
        }
    };

    float c[2][8][4] = {};

    load_chunk(0, 0);
    asm volatile("cp.async.commit_group;\n");

    for (int ch = 0; ch < NCHUNK; ch++) {
        if (ch + 1 < NCHUNK) {
            load_chunk((ch + 1) & 1, (ch + 1) * 32);
            asm volatile("cp.async.commit_group;\n");
            asm volatile("cp.async.wait_group 1;\n");
        } else {
            asm volatile("cp.async.wait_group 0;\n");
        }
        __syncthreads();
        const __half* cA = sA[ch & 1];
        const __half* cB = sB[ch & 1];
        #pragma unroll
        for (int kk = 0; kk < 2; kk++) {
            uint32_t a[2][4], bf[4][4];
            #pragma unroll
            for (int mt = 0; mt < 2; mt++) {
                uint32_t addr = (uint32_t)__cvta_generic_to_shared(
                    &cA[(wm * 32 + mt * 16 + (lane & 15)) * GP + ((lane >> 4) << 3) + kk * 16]);
                LDSM4(a[mt][0], a[mt][1], a[mt][2], a[mt][3], addr);
            }
            #pragma unroll
            for (int nt = 0; nt < 4; nt++) {
                uint32_t addr = (uint32_t)__cvta_generic_to_shared(
                    &cB[(wn * 64 + nt * 16 + ((lane & 7) + ((lane >> 4) << 3))) * GP + (lane & 8) + kk * 16]);
                LDSM4(bf[nt][0], bf[nt][1], bf[nt][2], bf[nt][3], addr);
            }
            #pragma unroll
            for (int mt = 0; mt < 2; mt++)
                #pragma unroll
                for (int nt = 0; nt < 4; nt++) {
                    MMA16816(c[mt][2 * nt],     a[mt], bf[nt][0], bf[nt][1]);
                    MMA16816(c[mt][2 * nt + 1], a[mt], bf[nt][2], bf[nt][3]);
                }
        }
        __syncthreads();
    }

    #pragma unroll
    for (int mt = 0; mt < 2; mt++) {
        int r0 = bm0 + wm * 32 + mt * 16 + (lane >> 2);
        #pragma unroll
        for (int nt8 = 0; nt8 < 8; nt8++) {
            int col = bn0 + wn * 64 + nt8 * 8 + 2 * (lane & 3);
            *reinterpret_cast<float2*>(&Y[(size_t)r0 * Nout + col]) =
                make_float2(c[mt][nt8][0], c[mt][nt8][1]);
            *reinterpret_cast<float2*>(&Y[(size_t)(r0 + 8) * Nout + col]) =
                make_float2(c[mt][nt8][2], c[mt][nt8][3]);
        }
    }
}

// ---------------- prep: l2norm + scale + concat + rotary -> fp16 -----------
__global__ void prep_kernel(const float* __restrict__ qx_scale,
                            const float* __restrict__ qa_scale,
                            const float* __restrict__ kx_scale,
                            const float* __restrict__ ka_scale) {
    int t = blockIdx.x;                 // global token 0..4095
    int b = t >> 11, n = t & (NN - 1);
    int w = threadIdx.x >> 5, l = threadIdx.x & 31;

    float c0 = g_cos[n * DH + l],      s0 = g_sin[n * DH + l];
    float c1 = g_cos[n * DH + l + 32], s1 = g_sin[n * DH + l + 32];
    const float SC = 0.08838834764831845f; // 1/sqrt(128)

    if (w < HEADS) {
        int h = w;
        const float* px = &g_qx[(size_t)t * DIM + h * DH];
        float x0 = px[l], x1 = px[l + 32];
        float sx = x0 * x0 + x1 * x1;
        #pragma unroll
        for (int o = 16; o; o >>= 1) sx += __shfl_xor_sync(0xFFFFFFFFu, sx, o);
        float rnx = 1.0f / fmaxf(sqrtf(sx), 1e-12f);
        float qx0 = x0 * rnx * qx_scale[h * DH + l];
        float qx1 = x1 * rnx * qx_scale[h * DH + l + 32];

        const float* pa = &g_qa[(size_t)t * DIM + h * DH];
        float a0 = pa[l], a1 = pa[l + 32];
        float sa = a0 * a0 + a1 * a1;
        #pragma unroll
        for (int o = 16; o; o >>= 1) sa += __shfl_xor_sync(0xFFFFFFFFu, sa, o);
        float rna = 1.0f / fmaxf(sqrtf(sa), 1e-12f);
        float qa0 = a0 * rna * qa_scale[h * DH + l];
        float qa1 = a1 * rna * qa_scale[h * DH + l + 32];

        __half* pq = &g_Qh[(((size_t)b * HEADS + h) * NN + n) * RD];
        pq[l]      = __float2half_rn(SC * (qx0 * c0 - qa0 * s0));
        pq[l + 64] = __float2half_rn(SC * (qa0 * c0 + qx0 * s0));
        pq[l + 32] = __float2half_rn(SC * (qx1 * c1 - qa1 * s1));
        pq[l + 96] = __float2half_rn(SC * (qa1 * c1 + qx1 * s1));
    } else if (w == 16) {   // K
        const float* px = &g_kvx[(size_t)t * 2 * DH];
        float x0 = px[l], x1 = px[l + 32];
        float sx = x0 * x0 + x1 * x1;
        #pragma unroll
        for (int o = 16; o; o >>= 1) sx += __shfl_xor_sync(0xFFFFFFFFu, sx, o);
        float rnx = 1.0f / fmaxf(sqrtf(sx), 1e-12f);
        float kx0 = x0 * rnx * kx_scale[l];
        float kx1 = x1 * rnx * kx_scale[l + 32];

        const float* pa = &g_kva[(size_t)t * 2 * DH];
        float a0 = pa[l], a1 = pa[l + 32];
        float sa = a0 * a0 + a1 * a1;
        #pragma unroll
        for (int o = 16; o; o >>= 1) sa += __shfl_xor_sync(0xFFFFFFFFu, sa, o);
        float rna = 1.0f / fmaxf(sqrtf(sa), 1e-12f);
        float ka0 = a0 * rna * ka_scale[l];
        float ka1 = a1 * rna * ka_scale[l + 32];

        __half* pk = &g_Kh[(size_t)t * RD];
        pk[l]      = __float2half_rn(kx0 * c0 - ka0 * s0);
        pk[l + 64] = __float2half_rn(ka0 * c0 + kx0 * s0);
        pk[l + 32] = __float2half_rn(kx1 * c1 - ka1 * s1);
        pk[l + 96] = __float2half_rn(ka1 * c1 + kx1 * s1);
    } else {                // V (no norm, no rotary)
        const float* px = &g_kvx[(size_t)t * 2 * DH + DH];
        const float* pa = &g_kva[(size_t)t * 2 * DH + DH];
        __half* pv = &g_Vh[(size_t)t * RD];
        pv[l]      = __float2half_rn(px[l]);
        pv[l + 32] = __float2half_rn(px[l + 32]);
        pv[l + 64] = __float2half_rn(pa[l]);
        pv[l + 96] = __float2half_rn(pa[l + 32]);
    }
}

// ---------------- tensor-core flash attention (fp16 mma, fp32 softmax) -----
#define PADW 136

__device__ __forceinline__ uint32_t pack_f16(float lo, float hi) {
    __half2 p = __floats2half2_rn(lo, hi);
    return *reinterpret_cast<uint32_t*>(&p);
}

__global__ void __launch_bounds__(256) attn_mma_kernel(float* __restrict__ out) {
    extern __shared__ __half sm[];
    __half* sK = sm;               // [64][PADW]
    __half* sV = sm + 64 * PADW;   // [64][PADW]

    const int qb = blockIdx.x, h = blockIdx.y, b = blockIdx.z;
    const int tid = threadIdx.x, w = tid >> 5, lane = tid & 31;
    const int q0 = w * 16;

    // ---- stage Q tile (128x128 fp16) into smem (aliases K|V), preload a-frags
    const __half* Qg = g_Qh + (((size_t)b * HEADS + h) * NN + (size_t)qb * 128) * RD;
    for (int i = tid; i < 128 * 16; i += 256) {
        int r = i >> 4, c = i & 15;
        *reinterpret_cast<uint4*>(&sm[r * PADW + c * 8]) =
            *reinterpret_cast<const uint4*>(&Qg[r * RD + c * 8]);
    }
    __syncthreads();

    uint32_t qa[8][4];
    {
        uint32_t qbase = (uint32_t)__cvta_generic_to_shared(
            &sm[(q0 + (lane & 15)) * PADW + ((lane >> 4) << 3)]);
        #pragma unroll
        for (int ks = 0; ks < 8; ks++) {
            uint32_t addr = qbase + ks * 16 * 2;
            LDSM4(qa[ks][0], qa[ks][1], qa[ks][2], qa[ks][3], addr);
        }
    }
    __syncthreads();   // Q reads done; smem reusable for K/V

    float m_[2] = {-INFINITY, -INFINITY};
    float l_[2] = {0.0f, 0.0f};
    float o[16][4] = {};

    const __half* Kg = g_Kh + (size_t)b * NN * RD;
    const __half* Vg = g_Vh + (size_t)b * NN * RD;

    const uint32_t kbase = (uint32_t)__cvta_generic_to_shared(
        &sK[((lane & 7) + ((lane >> 4) << 3)) * PADW + (lane & 8)]);
    const uint32_t vbase = (uint32_t)__cvta_generic_to_shared(
        &sV[(lane & 15) * PADW + ((lane >> 4) << 3)]);

    for (int kt = 0; kt < NN / 64; kt++) {
        __syncthreads();   // previous iteration's reads done
        {
            const __half* Kt = Kg + (size_t)kt * 64 * RD;
            const __half* Vt = Vg + (size_t)kt * 64 * RD;
            for (int i = tid; i < 64 * 16; i += 256) {
                int r = i >> 4, c = i & 15;
                *reinterpret_cast<uint4*>(&sK[r * PADW + c * 8]) =
                    *reinterpret_cast<const uint4*>(&Kt[r * RD + c * 8]);
                *reinterpret_cast<uint4*>(&sV[r * PADW + c * 8]) =
                    *reinterpret_cast<const uint4*>(&Vt[r * RD + c * 8]);
            }
        }
        __syncthreads();

        // ---- S = Q K^T
        float s[8][4] = {};
        #pragma unroll
        for (int ks = 0; ks < 8; ks++) {
            #pragma unroll
            for (int np = 0; np < 4; np++) {
                uint32_t addr = kbase + (uint32_t)((np * 16 * PADW + ks * 16) * 2);
                uint32_t b0, b1, b2, b3;
                LDSM4(b0, b1, b2, b3, addr);
                MMA16816(s[2 * np],     qa[ks], b0, b1);
                MMA16816(s[2 * np + 1], qa[ks], b2, b3);
            }
        }

        // ---- online softmax in registers
        float mnew[2], alpha[2], lsum[2];
        #pragma unroll
        for (int r = 0; r < 2; r++) {
            float mx = m_[r];
            #pragma unroll
            for (int nt = 0; nt < 8; nt++)
                mx = fmaxf(mx, fmaxf(s[nt][2 * r], s[nt][2 * r + 1]));
            mx = fmaxf(mx, __shfl_xor_sync(0xFFFFFFFFu, mx, 1));
            mx = fmaxf(mx, __shfl_xor_sync(0xFFFFFFFFu, mx, 2));
            mnew[r] = mx;
            alpha[r] = __expf(m_[r] - mx);
            lsum[r] = 0.0f;
        }
        #pragma unroll
        for (int nt = 0; nt < 8; nt++) {
            #pragma unroll
            for (int e = 0; e < 4; e++) {
                int r = e >> 1;
                float p = __expf(s[nt][e] - mnew[r]);
                s[nt][e] = p;
                lsum[r] += p;
            }
        }
        #pragma unroll
        for (int r = 0; r < 2; r++) {
            lsum[r] += __shfl_xor_sync(0xFFFFFFFFu, lsum[r], 1);
            lsum[r] += __shfl_xor_sync(0xFFFFFFFFu, lsum[r], 2);
            l_[r] = l_[r] * alpha[r] + lsum[r];
            m_[r] = mnew[r];
        }
        #pragma unroll
        for (int j = 0; j < 16; j++) {
            o[j][0] *= alpha[0]; o[j][1] *= alpha[0];
            o[j][2] *= alpha[1]; o[j][3] *= alpha[1];
        }

        // ---- O += P V
        #pragma unroll
        for (int ks2 = 0; ks2 < 4; ks2++) {
            uint32_t pa[4];
            pa[0] = pack_f16(s[2 * ks2][0],     s[2 * ks2][1]);
            pa[1] = pack_f16(s[2 * ks2][2],     s[2 * ks2][3]);
            pa[2] = pack_f16(s[2 * ks2 + 1][0], s[2 * ks2 + 1][1]);
            pa[3] = pack_f16(s[2 * ks2 + 1][2], s[2 * ks2 + 1][3]);
            #pragma unroll
            for (int np = 0; np < 8; np++) {
                uint32_t addr = vbase + (uint32_t)((ks2 * 16 * PADW + np * 16) * 2);
                uint32_t v0, v1, v2, v3;
                LDSM4T(v0, v1, v2, v3, addr);
                MMA16816(o[2 * np],     pa, v0, v1);
                MMA16816(o[2 * np + 1], pa, v2, v3);
            }
        }
    }

    // ---- normalize and store fp32: out[b][q][h*128+d]
    float rl0 = 1.0f / l_[0], rl1 = 1.0f / l_[1];
    int qrow = qb * 128 + q0 + (lane >> 2);
    #pragma unroll
    for (int j = 0; j < 16; j++) {
        int d = h * RD + j * 8 + 2 * (lane & 3);
        float* p0 = &out[((size_t)(b * NN + qrow)) * (HEADS * RD) + d];
        float* p1 = &out[((size_t)(b * NN + qrow + 8)) * (HEADS * RD) + d];
        *reinterpret_cast<float2*>(p0) = make_float2(o[j][0] * rl0, o[j][1] * rl0);
        *reinterpret_cast<float2*>(p1) = make_float2(o[j][2] * rl1, o[j][3] * rl1);
    }
}

// ---------------- launch ---------------------------------------------------
extern "C" void kernel_launch(void* const* d_in, const int* in_sizes, int n_in,
                              void* d_out, int out_size) {
    const float* x        = (const float*)d_in[0];
    const float* a        = (const float*)d_in[1];
    const float* Wq_x     = (const float*)d_in[2];
    const float* Wkv_x    = (const float*)d_in[3];
    const float* Wq_a     = (const float*)d_in[4];
    const float* Wkv_a    = (const float*)d_in[5];
    const float* qx_scale = (const float*)d_in[6];
    const float* qa_scale = (const float*)d_in[7];
    const float* kx_scale = (const float*)d_in[8];
    const float* ka_scale = (const float*)d_in[9];
    float* out = (float*)d_out;

    float *p_qx, *p_qa, *p_kvx, *p_kva;
    __half *p_xe, *p_ae, *p_wqxe, *p_wqae, *p_wkxe, *p_wkae;
    cudaGetSymbolAddress((void**)&p_qx,   g_qx);
    cudaGetSymbolAddress((void**)&p_qa,   g_qa);
    cudaGetSymbolAddress((void**)&p_kvx,  g_kvx);
    cudaGetSymbolAddress((void**)&p_kva,  g_kva);
    cudaGetSymbolAddress((void**)&p_xe,   g_xe);
    cudaGetSymbolAddress((void**)&p_ae,   g_ae);
    cudaGetSymbolAddress((void**)&p_wqxe, g_wqxe);
    cudaGetSymbolAddress((void**)&p_wqae, g_wqae);
    cudaGetSymbolAddress((void**)&p_wkxe, g_wkxe);
    cudaGetSymbolAddress((void**)&p_wkae, g_wkae);

    rope_invf_kernel<<<1, 64>>>();
    rope_table_kernel<<<(NN * DH + 255) / 256, 256>>>();

    // split-precision expansion
    split_expand_kernel<<<(NT * DIM + 255) / 256, 256>>>(x, p_xe, NT * DIM, 0);
    split_expand_kernel<<<(NT * DIM + 255) / 256, 256>>>(a, p_ae, NT * DIM, 0);
    split_expand_kernel<<<(DIM * DIM + 255) / 256, 256>>>(Wq_x, p_wqxe, DIM * DIM, 1);
    split_expand_kernel<<<(DIM * DIM + 255) / 256, 256>>>(Wq_a, p_wqae, DIM * DIM, 1);
    split_expand_kernel<<<(2 * DH * DIM + 255) / 256, 256>>>(Wkv_x, p_wkxe, 2 * DH * DIM, 1);
    split_expand_kernel<<<(2 * DH * DIM + 255) / 256, 256>>>(Wkv_a, p_wkae, 2 * DH * DIM, 1);

    // tensor-core projections
    hgemm_nt_kernel<<<dim3(DIM / 128, NT / 128), 256>>>(p_xe, p_wqxe, p_qx, DIM);
    hgemm_nt_kernel<<<dim3(DIM / 128, NT / 128), 256>>>(p_ae, p_wqae, p_qa, DIM);
    hgemm_nt_kernel<<<dim3(1, NT / 128), 256>>>(p_xe, p_wkxe, p_kvx, 2 * DH);
    hgemm_nt_kernel<<<dim3(1, NT / 128), 256>>>(p_ae, p_wkae, p_kva, 2 * DH);

    prep_kernel<<<NT, 18 * 32>>>(qx_scale, qa_scale, kx_scale, ka_scale);

    int smem_bytes = 2 * 64 * PADW * (int)sizeof(__half);  // 34816 B
    cudaFuncSetAttribute(attn_mma_kernel, cudaFuncAttributeMaxDynamicSharedMemorySize, smem_bytes);
    attn_mma_kernel<<<dim3(NN / 128, HEADS, BB), 256, smem_bytes>>>(out);
}

// round 9
// speedup vs baseline: 6.5645x; 1.3410x over previous
#include <cuda_runtime.h>
#include <cuda_fp16.h>
#include <math.h>
#include <stdint.h>

#define BB 2
#define NN 2048
#define DIM 1024
#define HEADS 16
#define DH 64
#define RD 128
#define NT (BB*NN)
#define K3 3072           // expanded K for split-precision fp16 GEMM
#define NCHUNK (K3/32)    // 96

// ---------------- scratch (static device globals; no allocation) ------------
__device__ float g_qx[(size_t)NT*DIM];       // x @ Wq_x^T
__device__ float g_qa[(size_t)NT*DIM];       // a @ Wq_a^T
__device__ float g_kvp[2][(size_t)2*NT*2*DH];// split-K partials: [khalf][which*NT*128 + t*128 + c]
__device__ __half g_Qh[(size_t)BB*HEADS*NN*RD]; // (b,h,n,128), pre-scaled 1/sqrt(128)
__device__ __half g_Kh[(size_t)NT*RD];          // (b,n,128)
__device__ __half g_Vh[(size_t)NT*RD];          // (b,n,128)
__device__ float g_cos[NN*DH];
__device__ float g_sin[NN*DH];
__device__ float g_invf[DH];

// expanded split-precision operands (hi|lo|hi for X, hi|hi|lo for W)
__device__ __half g_xe[(size_t)NT*K3];
__device__ __half g_ae[(size_t)NT*K3];
__device__ __half g_wqxe[(size_t)DIM*K3];
__device__ __half g_wqae[(size_t)DIM*K3];
__device__ __half g_wkxe[(size_t)2*DH*K3];
__device__ __half g_wkae[(size_t)2*DH*K3];

// ---------------- RoPE tables ----------------------------------------------
__global__ void rope_invf_kernel() {
    int j = threadIdx.x;
    if (j < DH) g_invf[j] = (float)pow(10000.0, -(double)j / 64.0);
}

__global__ void rope_table_kernel() {
    int i = blockIdx.x * blockDim.x + threadIdx.x;
    if (i >= NN * DH) return;
    int n = i >> 6, j = i & 63;
    float ang = (float)n * g_invf[j];        // fp32 multiply, as the reference
    const float HI = 6.28318548202514648f;
    const float LO = -1.7484556e-7f;
    float k = rintf(ang * 0.15915494309189535f);
    float r = fmaf(-k, HI, ang);
    r = fmaf(-k, LO, r);                     // r in [-pi, pi], err ~2e-7
    g_cos[i] = cosf(r);
    g_sin[i] = sinf(r);
}

// ---------------- split-precision expansion (vectorized x4) ----------------
// src: [rows,1024] fp32.  dst: [rows,3072] fp16.
// wmode=0 (activations): [hi | lo | hi];  wmode=1 (weights): [hi | hi | lo]
__global__ void split_expand_kernel(const float* __restrict__ src,
                                    __half* __restrict__ dst,
                                    int total, int wmode) {
    int i = blockIdx.x * blockDim.x + threadIdx.x;
    int i4 = i * 4;
    if (i4 >= total) return;
    int r = i4 >> 10, c = i4 & 1023;
    float4 v = *reinterpret_cast<const float4*>(&src[i4]);
    __half2 h01 = __floats2half2_rn(v.x, v.y);
    __half2 h23 = __floats2half2_rn(v.z, v.w);
    __half2 l01 = __floats2half2_rn(v.x - __half2float(__low2half(h01)),
                                    v.y - __half2float(__high2half(h01)));
    __half2 l23 = __floats2half2_rn(v.z - __half2float(__low2half(h23)),
                                    v.w - __half2float(__high2half(h23)));
    __half* d = dst + (size_t)r * K3;
    uint2 hv = make_uint2(*reinterpret_cast<uint32_t*>(&h01), *reinterpret_cast<uint32_t*>(&h23));
    uint2 lv = make_uint2(*reinterpret_cast<uint32_t*>(&l01), *reinterpret_cast<uint32_t*>(&l23));
    *reinterpret_cast<uint2*>(&d[c]) = hv;
    if (wmode) {
        *reinterpret_cast<uint2*>(&d[c + 1024]) = hv;
        *reinterpret_cast<uint2*>(&d[c + 2048]) = lv;
    } else {
        *reinterpret_cast<uint2*>(&d[c + 1024]) = lv;
        *reinterpret_cast<uint2*>(&d[c + 2048]) = hv;
    }
}

// ---------------- MMA helpers ----------------------------------------------
#define LDSM4(R0,R1,R2,R3,ADDR) \
    asm volatile("ldmatrix.sync.aligned.m8n8.x4.shared.b16 {%0,%1,%2,%3}, [%4];" \
        : "=r"(R0),"=r"(R1),"=r"(R2),"=r"(R3) : "r"(ADDR))
#define LDSM4T(R0,R1,R2,R3,ADDR) \
    asm volatile("ldmatrix.sync.aligned.m8n8.x4.trans.shared.b16 {%0,%1,%2,%3}, [%4];" \
        : "=r"(R0),"=r"(R1),"=r"(R2),"=r"(R3) : "r"(ADDR))
#define MMA16816(C, A, B0, B1) \
    asm volatile("mma.sync.aligned.m16n8k16.row.col.f32.f16.f16.f32 " \
        "{%0,%1,%2,%3},{%4,%5,%6,%7},{%8,%9},{%0,%1,%2,%3};" \
        : "+f"((C)[0]),"+f"((C)[1]),"+f"((C)[2]),"+f"((C)[3]) \
        : "r"((A)[0]),"r"((A)[1]),"r"((A)[2]),"r"((A)[3]), "r"(B0),"r"(B1))
#define CP_ASYNC16(DST, SRC) \
    asm volatile("cp.async.cg.shared.global [%0], [%1], 16;\n" :: "r"(DST), "l"(SRC))
#define CP_COMMIT() asm volatile("cp.async.commit_group;\n")

// ---------------- fp16 tensor-core NT GEMM core ----------------------------
// Block tile 128x128, 256 threads (8 warps: 4m x 2n), K-chunks of 32,
// cp.async double-buffered.  Ag/Bg pre-offset to block row/col.
#define GP 40   // smem row pitch in halves (32 data + 8 pad)

struct HgemmSmem { __half sA[2][128 * GP]; __half sB[2][128 * GP]; };

__device__ __forceinline__ void hgemm_core(const __half* __restrict__ Ag,
                                           const __half* __restrict__ Bg,
                                           float* __restrict__ Y, int Nout,
                                           int bm0, int bn0, int k0base, int nchunks,
                                           HgemmSmem* smem) {
    const int tid = threadIdx.x, lane = tid & 31, w = tid >> 5;
    const int wm = w & 3, wn = w >> 2;

    auto load_chunk = [&](int buf, int k0) {
        #pragma unroll
        for (int p = 0; p < 2; p++) {
            int idx = tid + p * 256;
            int row = idx >> 2, c8 = idx & 3;
            uint32_t da = (uint32_t)__cvta_generic_to_shared(&smem->sA[buf][row * GP + c8 * 8]);
            CP_ASYNC16(da, Ag + (size_t)row * K3 + k0 + c8 * 8);
            uint32_t db = (uint32_t)__cvta_generic_to_shared(&smem->sB[buf][row * GP + c8 * 8]);
            CP_ASYNC16(db, Bg + (size_t)row * K3 + k0 + c8 * 8);
        }
    };

    float c[2][8][4] = {};

    load_chunk(0, k0base);
    CP_COMMIT();

    for (int ch = 0; ch < nchunks; ch++) {
        if (ch + 1 < nchunks) {
            load_chunk((ch + 1) & 1, k0base + (ch + 1) * 32);
            CP_COMMIT();
            asm volatile("cp.async.wait_group 1;\n");
        } else {
            asm volatile("cp.async.wait_group 0;\n");
        }
        __syncthreads();
        const __half* cA = smem->sA[ch & 1];
        const __half* cB = smem->sB[ch & 1];
        #pragma unroll
        for (int kk = 0; kk < 2; kk++) {
            uint32_t a[2][4], bf[4][4];
            #pragma unroll
            for (int mt = 0; mt < 2; mt++) {
                uint32_t addr = (uint32_t)__cvta_generic_to_shared(
                    &cA[(wm * 32 + mt * 16 + (lane & 15)) * GP + ((lane >> 4) << 3) + kk * 16]);
                LDSM4(a[mt][0], a[mt][1], a[mt][2], a[mt][3], addr);
            }
            #pragma unroll
            for (int nt = 0; nt < 4; nt++) {
                uint32_t addr = (uint32_t)__cvta_generic_to_shared(
                    &cB[(wn * 64 + nt * 16 + ((lane & 7) + ((lane >> 4) << 3))) * GP + (lane & 8) + kk * 16]);
                LDSM4(bf[nt][0], bf[nt][1], bf[nt][2], bf[nt][3], addr);
            }
            #pragma unroll
            for (int mt = 0; mt < 2; mt++)
                #pragma unroll
                for (int nt = 0; nt < 4; nt++) {
                    MMA16816(c[mt][2 * nt],     a[mt], bf[nt][0], bf[nt][1]);
                    MMA16816(c[mt][2 * nt + 1], a[mt], bf[nt][2], bf[nt][3]);
                }
        }
        __syncthreads();
    }

    #pragma unroll
    for (int mt = 0; mt < 2; mt++) {
        int r0 = bm0 + wm * 32 + mt * 16 + (lane >> 2);
        #pragma unroll
        for (int nt8 = 0; nt8 < 8; nt8++) {
            int col = bn0 + wn * 64 + nt8 * 8 + 2 * (lane & 3);
            *reinterpret_cast<float2*>(&Y[(size_t)r0 * Nout + col]) =
                make_float2(c[mt][nt8][0], c[mt][nt8][1]);
            *reinterpret_cast<float2*>(&Y[(size_t)(r0 + 8) * Nout + col]) =
                make_float2(c[mt][nt8][2], c[mt][nt8][3]);
        }
    }
}

// Q projections: z=0 -> x@Wq_x, z=1 -> a@Wq_a
__global__ void __launch_bounds__(256) qproj_kernel() {
    __shared__ HgemmSmem smem;
    const __half* A = blockIdx.z ? g_ae : g_xe;
    const __half* B = blockIdx.z ? g_wqae : g_wqxe;
    float* Y = blockIdx.z ? g_qa : g_qx;
    int bm0 = blockIdx.y * 128, bn0 = blockIdx.x * 128;
    hgemm_core(A + (size_t)bm0 * K3, B + (size_t)bn0 * K3, Y, DIM, bm0, bn0, 0, NCHUNK, &smem);
}

// KV projections: z bit0 -> which (x/a), z bit1 -> K half (split-K)
__global__ void __launch_bounds__(256) kvproj_kernel() {
    __shared__ HgemmSmem smem;
    int which = blockIdx.z & 1, kh = blockIdx.z >> 1;
    const __half* A = which ? g_ae : g_xe;
    const __half* B = which ? g_wkae : g_wkxe;
    float* Y = &g_kvp[kh][(size_t)which * NT * 128];
    int bm0 = blockIdx.y * 128;
    hgemm_core(A + (size_t)bm0 * K3, B, Y, 128, bm0, 0, kh * (K3 / 2), NCHUNK / 2, &smem);
}

// ---------------- prep: l2norm + scale + concat + rotary -> fp16 -----------
// kv values come as split-K partial sums: g_kvp[0] + g_kvp[1]
__global__ void prep_kernel(const float* __restrict__ qx_scale,
                            const float* __restrict__ qa_scale,
                            const float* __restrict__ kx_scale,
                            const float* __restrict__ ka_scale) {
    int t = blockIdx.x;                 // global token 0..4095
    int b = t >> 11, n = t & (NN - 1);
    int w = threadIdx.x >> 5, l = threadIdx.x & 31;

    float c0 = g_cos[n * DH + l],      s0 = g_sin[n * DH + l];
    float c1 = g_cos[n * DH + l + 32], s1 = g_sin[n * DH + l + 32];
    const float SC = 0.08838834764831845f; // 1/sqrt(128)

    if (w < HEADS) {
        int h = w;
        const float* px = &g_qx[(size_t)t * DIM + h * DH];
        float x0 = px[l], x1 = px[l + 32];
        float sx = x0 * x0 + x1 * x1;
        #pragma unroll
        for (int o = 16; o; o >>= 1) sx += __shfl_xor_sync(0xFFFFFFFFu, sx, o);
        float rnx = 1.0f / fmaxf(sqrtf(sx), 1e-12f);
        float qx0 = x0 * rnx * qx_scale[h * DH + l];
        float qx1 = x1 * rnx * qx_scale[h * DH + l + 32];

        const float* pa = &g_qa[(size_t)t * DIM + h * DH];
        float a0 = pa[l], a1 = pa[l + 32];
        float sa = a0 * a0 + a1 * a1;
        #pragma unroll
        for (int o = 16; o; o >>= 1) sa += __shfl_xor_sync(0xFFFFFFFFu, sa, o);
        float rna = 1.0f / fmaxf(sqrtf(sa), 1e-12f);
        float qa0 = a0 * rna * qa_scale[h * DH + l];
        float qa1 = a1 * rna * qa_scale[h * DH + l + 32];

        __half* pq = &g_Qh[(((size_t)b * HEADS + h) * NN + n) * RD];
        pq[l]      = __float2half_rn(SC * (qx0 * c0 - qa0 * s0));
        pq[l + 64] = __float2half_rn(SC * (qa0 * c0 + qx0 * s0));
        pq[l + 32] = __float2half_rn(SC * (qx1 * c1 - qa1 * s1));
        pq[l + 96] = __float2half_rn(SC * (qa1 * c1 + qx1 * s1));
    } else if (w == 16) {   // K
        size_t bx = (size_t)t * 128;               // kv_x partials
        size_t ba = (size_t)NT * 128 + bx;         // kv_a partials
        float x0 = g_kvp[0][bx + l] + g_kvp[1][bx + l];
        float x1 = g_kvp[0][bx + l + 32] + g_kvp[1][bx + l + 32];
        float sx = x0 * x0 + x1 * x1;
        #pragma unroll
        for (int o = 16; o; o >>= 1) sx += __shfl_xor_sync(0xFFFFFFFFu, sx, o);
        float rnx = 1.0f / fmaxf(sqrtf(sx), 1e-12f);
        float kx0 = x0 * rnx * kx_scale[l];
        float kx1 = x1 * rnx * kx_scale[l + 32];

        float a0 = g_kvp[0][ba + l] + g_kvp[1][ba + l];
        float a1 = g_kvp[0][ba + l + 32] + g_kvp[1][ba + l + 32];
        float sa = a0 * a0 + a1 * a1;
        #pragma unroll
        for (int o = 16; o; o >>= 1) sa += __shfl_xor_sync(0xFFFFFFFFu, sa, o);
        float rna = 1.0f / fmaxf(sqrtf(sa), 1e-12f);
        float ka0 = a0 * rna * ka_scale[l];
        float ka1 = a1 * rna * ka_scale[l + 32];

        __half* pk = &g_Kh[(size_t)t * RD];
        pk[l]      = __float2half_rn(kx0 * c0 - ka0 * s0);
        pk[l + 64] = __float2half_rn(ka0 * c0 + kx0 * s0);
        pk[l + 32] = __float2half_rn(kx1 * c1 - ka1 * s1);
        pk[l + 96] = __float2half_rn(ka1 * c1 + kx1 * s1);
    } else {                // V (no norm, no rotary)
        size_t bx = (size_t)t * 128 + DH;
        size_t ba = (size_t)NT * 128 + bx;
        __half* pv = &g_Vh[(size_t)t * RD];
        pv[l]      = __float2half_rn(g_kvp[0][bx + l] + g_kvp[1][bx + l]);
        pv[l + 32] = __float2half_rn(g_kvp[0][bx + l + 32] + g_kvp[1][bx + l + 32]);
        pv[l + 64] = __float2half_rn(g_kvp[0][ba + l] + g_kvp[1][ba + l]);
        pv[l + 96] = __float2half_rn(g_kvp[0][ba + l + 32] + g_kvp[1][ba + l + 32]);
    }
}

// ---------------- tensor-core flash attention (fp16 mma, cp.async pipeline) -
// smem: sK[2][64][PADW] | sV[2][64][PADW] fp16 (Q staging aliases first 128 rows)
#define PADW 136
#define TILE_H (64 * PADW)   // halves per buffer

__device__ __forceinline__ uint32_t pack_f16(float lo, float hi) {
    __half2 p = __floats2half2_rn(lo, hi);
    return *reinterpret_cast<uint32_t*>(&p);
}

__global__ void __launch_bounds__(256) attn_mma_kernel(float* __restrict__ out) {
    extern __shared__ __half sm[];
    // buffers: sK0 @0, sK1 @TILE_H, sV0 @2*TILE_H, sV1 @3*TILE_H

    const int qb = blockIdx.x, h = blockIdx.y, b = blockIdx.z;
    const int tid = threadIdx.x, w = tid >> 5, lane = tid & 31;
    const int q0 = w * 16;

    // ---- stage Q tile (128x128 fp16) into smem (aliases sK0|sK1), preload a-frags
    const __half* Qg = g_Qh + (((size_t)b * HEADS + h) * NN + (size_t)qb * 128) * RD;
    for (int i = tid; i < 128 * 16; i += 256) {
        int r = i >> 4, c = i & 15;
        *reinterpret_cast<uint4*>(&sm[r * PADW + c * 8]) =
            *reinterpret_cast<const uint4*>(&Qg[r * RD + c * 8]);
    }
    __syncthreads();

    uint32_t qa[8][4];
    {
        uint32_t qbase = (uint32_t)__cvta_generic_to_shared(
            &sm[(q0 + (lane & 15)) * PADW + ((lane >> 4) << 3)]);
        #pragma unroll
        for (int ks = 0; ks < 8; ks++) {
            uint32_t addr = qbase + ks * 16 * 2;
            LDSM4(qa[ks][0], qa[ks][1], qa[ks][2], qa[ks][3], addr);
        }
    }
    __syncthreads();   // Q reads done; smem reusable for K/V

    float m_[2] = {-INFINITY, -INFINITY};
    float l_[2] = {0.0f, 0.0f};
    float o[16][4] = {};

    const __half* Kg = g_Kh + (size_t)b * NN * RD;
    const __half* Vg = g_Vh + (size_t)b * NN * RD;

    const uint32_t kbase0 = (uint32_t)__cvta_generic_to_shared(
        &sm[((lane & 7) + ((lane >> 4) << 3)) * PADW + (lane & 8)]);
    const uint32_t vbase0 = (uint32_t)__cvta_generic_to_shared(
        &sm[2 * TILE_H + (lane & 15) * PADW + ((lane >> 4) << 3)]);

    auto prefetch = [&](int kt, int buf) {
        const __half* Kt = Kg + (size_t)kt * 64 * RD;
        const __half* Vt = Vg + (size_t)kt * 64 * RD;
        __half* dK = sm + buf * TILE_H;
        __half* dV = sm + (2 + buf) * TILE_H;
        #pragma unroll
        for (int p = 0; p < 4; p++) {
            int idx = tid + p * 256;
            int r = idx >> 4, c8 = idx & 15;
            uint32_t dk = (uint32_t)__cvta_generic_to_shared(&dK[r * PADW + c8 * 8]);
            CP_ASYNC16(dk, Kt + (size_t)r * RD + c8 * 8);
            uint32_t dv = (uint32_t)__cvta_generic_to_shared(&dV[r * PADW + c8 * 8]);
            CP_ASYNC16(dv, Vt + (size_t)r * RD + c8 * 8);
        }
    };

    prefetch(0, 0);
    CP_COMMIT();

    for (int kt = 0; kt < NN / 64; kt++) {
        if (kt + 1 < NN / 64) {
            prefetch(kt + 1, (kt + 1) & 1);
            CP_COMMIT();
            asm volatile("cp.async.wait_group 1;\n");
        } else {
            asm volatile("cp.async.wait_group 0;\n");
        }
        __syncthreads();   // tile kt visible to all warps

        const uint32_t bufoff = (uint32_t)((kt & 1) * TILE_H * 2);  // bytes
        const uint32_t kbase = kbase0 + bufoff;
        const uint32_t vbase = vbase0 + bufoff;

        // ---- S = Q K^T
        float s[8][4] = {};
        #pragma unroll
        for (int ks = 0; ks < 8; ks++) {
            #pragma unroll
            for (int np = 0; np < 4; np++) {
                uint32_t addr = kbase + (uint32_t)((np * 16 * PADW + ks * 16) * 2);
                uint32_t b0, b1, b2, b3;
                LDSM4(b0, b1, b2, b3, addr);
                MMA16816(s[2 * np],     qa[ks], b0, b1);
                MMA16816(s[2 * np + 1], qa[ks], b2, b3);
            }
        }

        // ---- online softmax in registers
        float mnew[2], alpha[2], lsum[2];
        #pragma unroll
        for (int r = 0; r < 2; r++) {
            float mx = m_[r];
            #pragma unroll
            for (int nt = 0; nt < 8; nt++)
                mx = fmaxf(mx, fmaxf(s[nt][2 * r], s[nt][2 * r + 1]));
            mx = fmaxf(mx, __shfl_xor_sync(0xFFFFFFFFu, mx, 1));
            mx = fmaxf(mx, __shfl_xor_sync(0xFFFFFFFFu, mx, 2));
            mnew[r] = mx;
            alpha[r] = __expf(m_[r] - mx);
            lsum[r] = 0.0f;
        }
        #pragma unroll
        for (int nt = 0; nt < 8; nt++) {
            #pragma unroll
            for (int e = 0; e < 4; e++) {
                int r = e >> 1;
                float p = __expf(s[nt][e] - mnew[r]);
                s[nt][e] = p;
                lsum[r] += p;
            }
        }
        #pragma unroll
        for (int r = 0; r < 2; r++) {
            lsum[r] += __shfl_xor_sync(0xFFFFFFFFu, lsum[r], 1);
            lsum[r] += __shfl_xor_sync(0xFFFFFFFFu, lsum[r], 2);
            l_[r] = l_[r] * alpha[r] + lsum[r];
            m_[r] = mnew[r];
        }
        #pragma unroll
        for (int j = 0; j < 16; j++) {
            o[j][0] *= alpha[0]; o[j][1] *= alpha[0];
            o[j][2] *= alpha[1]; o[j][3] *= alpha[1];
        }

        // ---- O += P V
        #pragma unroll
        for (int ks2 = 0; ks2 < 4; ks2++) {
            uint32_t pa[4];
            pa[0] = pack_f16(s[2 * ks2][0],     s[2 * ks2][1]);
            pa[1] = pack_f16(s[2 * ks2][2],     s[2 * ks2][3]);
            pa[2] = pack_f16(s[2 * ks2 + 1][0], s[2 * ks2 + 1][1]);
            pa[3] = pack_f16(s[2 * ks2 + 1][2], s[2 * ks2 + 1][3]);
            #pragma unroll
            for (int np = 0; np < 8; np++) {
                uint32_t addr = vbase + (uint32_t)((ks2 * 16 * PADW + np * 16) * 2);
                uint32_t v0, v1, v2, v3;
                LDSM4T(v0, v1, v2, v3, addr);
                MMA16816(o[2 * np],     pa, v0, v1);
                MMA16816(o[2 * np + 1], pa, v2, v3);
            }
        }
        __syncthreads();   // all warps done reading buf[kt&1] before kt+2 prefetch
    }

    // ---- normalize and store fp32: out[b][q][h*128+d]
    float rl0 = 1.0f / l_[0], rl1 = 1.0f / l_[1];
    int qrow = qb * 128 + q0 + (lane >> 2);
    #pragma unroll
    for (int j = 0; j < 16; j++) {
        int d = h * RD + j * 8 + 2 * (lane & 3);
        float* p0 = &out[((size_t)(b * NN + qrow)) * (HEADS * RD) + d];
        float* p1 = &out[((size_t)(b * NN + qrow + 8)) * (HEADS * RD) + d];
        *reinterpret_cast<float2*>(p0) = make_float2(o[j][0] * rl0, o[j][1] * rl0);
        *reinterpret_cast<float2*>(p1) = make_float2(o[j][2] * rl1, o[j][3] * rl1);
    }
}

// ---------------- launch ---------------------------------------------------
extern "C" void kernel_launch(void* const* d_in, const int* in_sizes, int n_in,
                              void* d_out, int out_size) {
    const float* x        = (const float*)d_in[0];
    const float* a        = (const float*)d_in[1];
    const float* Wq_x     = (const float*)d_in[2];
    const float* Wkv_x    = (const float*)d_in[3];
    const float* Wq_a     = (const float*)d_in[4];
    const float* Wkv_a    = (const float*)d_in[5];
    const float* qx_scale = (const float*)d_in[6];
    const float* qa_scale = (const float*)d_in[7];
    const float* kx_scale = (const float*)d_in[8];
    const float* ka_scale = (const float*)d_in[9];
    float* out = (float*)d_out;

    __half *p_xe, *p_ae, *p_wqxe, *p_wqae, *p_wkxe, *p_wkae;
    cudaGetSymbolAddress((void**)&p_xe,   g_xe);
    cudaGetSymbolAddress((void**)&p_ae,   g_ae);
    cudaGetSymbolAddress((void**)&p_wqxe, g_wqxe);
    cudaGetSymbolAddress((void**)&p_wqae, g_wqae);
    cudaGetSymbolAddress((void**)&p_wkxe, g_wkxe);
    cudaGetSymbolAddress((void**)&p_wkae, g_wkae);

    rope_invf_kernel<<<1, 64>>>();
    rope_table_kernel<<<(NN * DH + 255) / 256, 256>>>();

    // split-precision expansion (4 elems/thread)
    split_expand_kernel<<<(NT * DIM / 4 + 255) / 256, 256>>>(x, p_xe, NT * DIM, 0);
    split_expand_kernel<<<(NT * DIM / 4 + 255) / 256, 256>>>(a, p_ae, NT * DIM, 0);
    split_expand_kernel<<<(DIM * DIM / 4 + 255) / 256, 256>>>(Wq_x, p_wqxe, DIM * DIM, 1);
    split_expand_kernel<<<(DIM * DIM / 4 + 255) / 256, 256>>>(Wq_a, p_wqae, DIM * DIM, 1);
    split_expand_kernel<<<(2 * DH * DIM / 4 + 255) / 256, 256>>>(Wkv_x, p_wkxe, 2 * DH * DIM, 1);
    split_expand_kernel<<<(2 * DH * DIM / 4 + 255) / 256, 256>>>(Wkv_a, p_wkae, 2 * DH * DIM, 1);

    // tensor-core projections (batched)
    qproj_kernel<<<dim3(DIM / 128, NT / 128, 2), 256>>>();
    kvproj_kernel<<<dim3(1, NT / 128, 4), 256>>>();

    prep_kernel<<<NT, 18 * 32>>>(qx_scale, qa_scale, kx_scale, ka_scale);

    int smem_bytes = 4 * TILE_H * (int)sizeof(__half);  // 69632 B
    cudaFuncSetAttribute(attn_mma_kernel, cudaFuncAttributeMaxDynamicSharedMemorySize, smem_bytes);
    attn_mma_kernel<<<dim3(NN / 128, HEADS, BB), 256, smem_bytes>>>(out);
}

// round 10
// speedup vs baseline: 6.9287x; 1.0555x over previous
#include <cuda_runtime.h>
#include <cuda_fp16.h>
#include <math.h>
#include <stdint.h>

#define BB 2
#define NN 2048
#define DIM 1024
#define HEADS 16
#define DH 64
#define RD 128
#define NT (BB*NN)
#define K3 3072           // expanded K for split-precision fp16 GEMM
#define NCHUNK (K3/32)    // 96

// ---------------- scratch (static device globals; no allocation) ------------
__device__ float g_qx[(size_t)NT*DIM];       // x @ Wq_x^T
__device__ float g_qa[(size_t)NT*DIM];       // a @ Wq_a^T
__device__ float g_kvp[2][(size_t)2*NT*2*DH];// split-K partials: [khalf][which*NT*128 + t*128 + c]
__device__ __half g_Qh[(size_t)BB*HEADS*NN*RD]; // (b,h,n,128), pre-scaled log2e/sqrt(128)
__device__ __half g_Kh[(size_t)NT*RD];          // (b,n,128)
__device__ __half g_Vh[(size_t)NT*RD];          // (b,n,128)
__device__ float g_cos[NN*DH];
__device__ float g_sin[NN*DH];
__device__ float g_invf[DH];

// expanded split-precision operands (hi|lo|hi for X, hi|hi|lo for W)
__device__ __half g_xe[(size_t)NT*K3];
__device__ __half g_ae[(size_t)NT*K3];
__device__ __half g_wqxe[(size_t)DIM*K3];
__device__ __half g_wqae[(size_t)DIM*K3];
__device__ __half g_wkxe[(size_t)2*DH*K3];
__device__ __half g_wkae[(size_t)2*DH*K3];

// ---------------- RoPE tables ----------------------------------------------
__global__ void rope_invf_kernel() {
    int j = threadIdx.x;
    if (j < DH) g_invf[j] = (float)pow(10000.0, -(double)j / 64.0);
}

__global__ void rope_table_kernel() {
    int i = blockIdx.x * blockDim.x + threadIdx.x;
    if (i >= NN * DH) return;
    int n = i >> 6, j = i & 63;
    float ang = (float)n * g_invf[j];        // fp32 multiply, as the reference
    const float HI = 6.28318548202514648f;
    const float LO = -1.7484556e-7f;
    float k = rintf(ang * 0.15915494309189535f);
    float r = fmaf(-k, HI, ang);
    r = fmaf(-k, LO, r);                     // r in [-pi, pi], err ~2e-7
    g_cos[i] = cosf(r);
    g_sin[i] = sinf(r);
}

// ---------------- split-precision expansion (all 6 tensors, one launch) -----
// per-tensor: src [rows,1024] fp32 -> dst [rows,3072] fp16
// wmode=0 (activations): [hi | lo | hi];  wmode=1 (weights): [hi | hi | lo]
#define XV4   (NT*DIM/4)       // 1048576 vec4s -> 4096 blocks
#define WQV4  (DIM*DIM/4)      // 262144 -> 1024 blocks
#define WKV4  (2*DH*DIM/4)     // 32768 -> 128 blocks

__device__ __forceinline__ void expand_one(const float* __restrict__ src,
                                           __half* __restrict__ dst,
                                           int i4, int wmode) {
    int r = i4 >> 8, c = (i4 & 255) * 4;   // i4 indexes vec4 within [rows,1024]
    float4 v = *reinterpret_cast<const float4*>(&src[(size_t)r * 1024 + c]);
    __half2 h01 = __floats2half2_rn(v.x, v.y);
    __half2 h23 = __floats2half2_rn(v.z, v.w);
    __half2 l01 = __floats2half2_rn(v.x - __half2float(__low2half(h01)),
                                    v.y - __half2float(__high2half(h01)));
    __half2 l23 = __floats2half2_rn(v.z - __half2float(__low2half(h23)),
                                    v.w - __half2float(__high2half(h23)));
    __half* d = dst + (size_t)r * K3;
    uint2 hv = make_uint2(*reinterpret_cast<uint32_t*>(&h01), *reinterpret_cast<uint32_t*>(&h23));
    uint2 lv = make_uint2(*reinterpret_cast<uint32_t*>(&l01), *reinterpret_cast<uint32_t*>(&l23));
    *reinterpret_cast<uint2*>(&d[c]) = hv;
    if (wmode) {
        *reinterpret_cast<uint2*>(&d[c + 1024]) = hv;
        *reinterpret_cast<uint2*>(&d[c + 2048]) = lv;
    } else {
        *reinterpret_cast<uint2*>(&d[c + 1024]) = lv;
        *reinterpret_cast<uint2*>(&d[c + 2048]) = hv;
    }
}

__global__ void expand_all_kernel(const float* __restrict__ x, const float* __restrict__ a,
                                  const float* __restrict__ wqx, const float* __restrict__ wqa,
                                  const float* __restrict__ wkx, const float* __restrict__ wka) {
    int i = blockIdx.x * blockDim.x + threadIdx.x;
    if (i < XV4)                      { expand_one(x,   g_xe,   i, 0); return; }
    i -= XV4;
    if (i < XV4)                      { expand_one(a,   g_ae,   i, 0); return; }
    i -= XV4;
    if (i < WQV4)                     { expand_one(wqx, g_wqxe, i, 1); return; }
    i -= WQV4;
    if (i < WQV4)                     { expand_one(wqa, g_wqae, i, 1); return; }
    i -= WQV4;
    if (i < WKV4)                     { expand_one(wkx, g_wkxe, i, 1); return; }
    i -= WKV4;
    if (i < WKV4)                     { expand_one(wka, g_wkae, i, 1); }
}

// ---------------- MMA helpers ----------------------------------------------
#define LDSM4(R0,R1,R2,R3,ADDR) \
    asm volatile("ldmatrix.sync.aligned.m8n8.x4.shared.b16 {%0,%1,%2,%3}, [%4];" \
        : "=r"(R0),"=r"(R1),"=r"(R2),"=r"(R3) : "r"(ADDR))
#define LDSM4T(R0,R1,R2,R3,ADDR) \
    asm volatile("ldmatrix.sync.aligned.m8n8.x4.trans.shared.b16 {%0,%1,%2,%3}, [%4];" \
        : "=r"(R0),"=r"(R1),"=r"(R2),"=r"(R3) : "r"(ADDR))
#define MMA16816(C, A, B0, B1) \
    asm volatile("mma.sync.aligned.m16n8k16.row.col.f32.f16.f16.f32 " \
        "{%0,%1,%2,%3},{%4,%5,%6,%7},{%8,%9},{%0,%1,%2,%3};" \
        : "+f"((C)[0]),"+f"((C)[1]),"+f"((C)[2]),"+f"((C)[3]) \
        : "r"((A)[0]),"r"((A)[1]),"r"((A)[2]),"r"((A)[3]), "r"(B0),"r"(B1))
#define CP_ASYNC16(DST, SRC) \
    asm volatile("cp.async.cg.shared.global [%0], [%1], 16;\n" :: "r"(DST), "l"(SRC))
#define CP_COMMIT() asm volatile("cp.async.commit_group;\n")

// ---------------- unified projection GEMM: 256x128 tiles, 512 threads -------
// Y[M,Nout] = A[M,K3] @ B[Nout,K3]^T, fp32 out.
// One launch covers: 256 CTAs Q-proj (2 x 16m x 8n) + 64 CTAs KV-proj
// (2 which x 16m x 2 split-K halves).
#define GP 40   // smem row pitch in halves (32 data + 8 pad)
#define SA_H (256*GP)
#define SB_H (128*GP)
#define PROJ_SMEM ((2*SA_H + 2*SB_H) * 2)   // bytes: 122880? no: (20480+10240)*2 halves *2B

__global__ void __launch_bounds__(512, 1) proj_kernel() {
    extern __shared__ __half ps[];
    __half* sA = ps;                  // [2][256*GP]
    __half* sB = ps + 2 * SA_H;       // [2][128*GP]

    const int tid = threadIdx.x, lane = tid & 31, w = tid >> 5;
    const int wm = w & 3, wn = w >> 2;

    const __half* Ag; const __half* Bg; float* Y;
    int Nout, bm0, bn0, k0base, nchunks;
    {
        int id = blockIdx.x;
        if (id < 256) {               // Q projections
            int which = id >> 7;
            int rem = id & 127;
            int mb = rem >> 3, nb = rem & 7;
            Ag = which ? g_ae : g_xe;
            Bg = which ? g_wqae : g_wqxe;
            Y  = which ? g_qa : g_qx;
            Nout = DIM; bm0 = mb * 256; bn0 = nb * 128;
            k0base = 0; nchunks = NCHUNK;
        } else {                      // KV projections, split-K 2
            int id2 = id - 256;
            int mb = id2 & 15, which = (id2 >> 4) & 1, kh = id2 >> 5;
            Ag = which ? g_ae : g_xe;
            Bg = which ? g_wkae : g_wkxe;
            Y  = &g_kvp[kh][(size_t)which * NT * 128];
            Nout = 128; bm0 = mb * 256; bn0 = 0;
            k0base = kh * (K3 / 2); nchunks = NCHUNK / 2;
        }
        Ag += (size_t)bm0 * K3;
        Bg += (size_t)bn0 * K3;
    }

    auto load_chunk = [&](int buf, int k0) {
        // A: 256 rows x 32 halves = 1024 x 16B; 2 per thread
        #pragma unroll
        for (int p = 0; p < 2; p++) {
            int idx = tid + p * 512;
            int row = idx >> 2, c8 = idx & 3;
            uint32_t da = (uint32_t)__cvta_generic_to_shared(&sA[buf * SA_H + row * GP + c8 * 8]);
            CP_ASYNC16(da, Ag + (size_t)row * K3 + k0 + c8 * 8);
        }
        // B: 128 rows x 32 halves = 512 x 16B; 1 per thread
        {
            int row = tid >> 2, c8 = tid & 3;
            uint32_t db = (uint32_t)__cvta_generic_to_shared(&sB[buf * SB_H + row * GP + c8 * 8]);
            CP_ASYNC16(db, Bg + (size_t)row * K3 + k0 + c8 * 8);
        }
    };

    float c[4][4][4] = {};   // mt x n8 x frag

    load_chunk(0, k0base);
    CP_COMMIT();

    for (int ch = 0; ch < nchunks; ch++) {
        if (ch + 1 < nchunks) {
            load_chunk((ch + 1) & 1, k0base + (ch + 1) * 32);
            CP_COMMIT();
            asm volatile("cp.async.wait_group 1;\n");
        } else {
            asm volatile("cp.async.wait_group 0;\n");
        }
        __syncthreads();
        const __half* cA = sA + (ch & 1) * SA_H;
        const __half* cB = sB + (ch & 1) * SB_H;
        #pragma unroll
        for (int kk = 0; kk < 2; kk++) {
            uint32_t a[4][4], bf[2][4];
            #pragma unroll
            for (int mt = 0; mt < 4; mt++) {
                uint32_t addr = (uint32_t)__cvta_generic_to_shared(
                    &cA[(wm * 64 + mt * 16 + (lane & 15)) * GP + ((lane >> 4) << 3) + kk * 16]);
                LDSM4(a[mt][0], a[mt][1], a[mt][2], a[mt][3], addr);
            }
            #pragma unroll
            for (int nt = 0; nt < 2; nt++) {
                uint32_t addr = (uint32_t)__cvta_generic_to_shared(
                    &cB[(wn * 32 + nt * 16 + ((lane & 7) + ((lane >> 4) << 3))) * GP + (lane & 8) + kk * 16]);
                LDSM4(bf[nt][0], bf[nt][1], bf[nt][2], bf[nt][3], addr);
            }
            #pragma unroll
            for (int mt = 0; mt < 4; mt++)
                #pragma unroll
                for (int nt = 0; nt < 2; nt++) {
                    MMA16816(c[mt][2 * nt],     a[mt], bf[nt][0], bf[nt][1]);
                    MMA16816(c[mt][2 * nt + 1], a[mt], bf[nt][2], bf[nt][3]);
                }
        }
        __syncthreads();
    }

    #pragma unroll
    for (int mt = 0; mt < 4; mt++) {
        int r0 = bm0 + wm * 64 + mt * 16 + (lane >> 2);
        #pragma unroll
        for (int n8 = 0; n8 < 4; n8++) {
            int col = bn0 + wn * 32 + n8 * 8 + 2 * (lane & 3);
            *reinterpret_cast<float2*>(&Y[(size_t)r0 * Nout + col]) =
                make_float2(c[mt][n8][0], c[mt][n8][1]);
            *reinterpret_cast<float2*>(&Y[(size_t)(r0 + 8) * Nout + col]) =
                make_float2(c[mt][n8][2], c[mt][n8][3]);
        }
    }
}

// ---------------- prep: l2norm + scale + concat + rotary -> fp16 -----------
// Q is additionally scaled by log2(e)/sqrt(128) so attention can use exp2.
__global__ void prep_kernel(const float* __restrict__ qx_scale,
                            const float* __restrict__ qa_scale,
                            const float* __restrict__ kx_scale,
                            const float* __restrict__ ka_scale) {
    int t = blockIdx.x;                 // global token 0..4095
    int b = t >> 11, n = t & (NN - 1);
    int w = threadIdx.x >> 5, l = threadIdx.x & 31;

    float c0 = g_cos[n * DH + l],      s0 = g_sin[n * DH + l];
    float c1 = g_cos[n * DH + l + 32], s1 = g_sin[n * DH + l + 32];
    const float SC = 0.08838834764831845f * 1.44269504088896341f; // log2e/sqrt(128)

    if (w < HEADS) {
        int h = w;
        const float* px = &g_qx[(size_t)t * DIM + h * DH];
        float x0 = px[l], x1 = px[l + 32];
        float sx = x0 * x0 + x1 * x1;
        #pragma unroll
        for (int o = 16; o; o >>= 1) sx += __shfl_xor_sync(0xFFFFFFFFu, sx, o);
        float rnx = 1.0f / fmaxf(sqrtf(sx), 1e-12f);
        float qx0 = x0 * rnx * qx_scale[h * DH + l];
        float qx1 = x1 * rnx * qx_scale[h * DH + l + 32];

        const float* pa = &g_qa[(size_t)t * DIM + h * DH];
        float a0 = pa[l], a1 = pa[l + 32];
        float sa = a0 * a0 + a1 * a1;
        #pragma unroll
        for (int o = 16; o; o >>= 1) sa += __shfl_xor_sync(0xFFFFFFFFu, sa, o);
        float rna = 1.0f / fmaxf(sqrtf(sa), 1e-12f);
        float qa0 = a0 * rna * qa_scale[h * DH + l];
        float qa1 = a1 * rna * qa_scale[h * DH + l + 32];

        __half* pq = &g_Qh[(((size_t)b * HEADS + h) * NN + n) * RD];
        pq[l]      = __float2half_rn(SC * (qx0 * c0 - qa0 * s0));
        pq[l + 64] = __float2half_rn(SC * (qa0 * c0 + qx0 * s0));
        pq[l + 32] = __float2half_rn(SC * (qx1 * c1 - qa1 * s1));
        pq[l + 96] = __float2half_rn(SC * (qa1 * c1 + qx1 * s1));
    } else if (w == 16) {   // K
        size_t bx = (size_t)t * 128;               // kv_x partials
        size_t ba = (size_t)NT * 128 + bx;         // kv_a partials
        float x0 = g_kvp[0][bx + l] + g_kvp[1][bx + l];
        float x1 = g_kvp[0][bx + l + 32] + g_kvp[1][bx + l + 32];
        float sx = x0 * x0 + x1 * x1;
        #pragma unroll
        for (int o = 16; o; o >>= 1) sx += __shfl_xor_sync(0xFFFFFFFFu, sx, o);
        float rnx = 1.0f / fmaxf(sqrtf(sx), 1e-12f);
        float kx0 = x0 * rnx * kx_scale[l];
        float kx1 = x1 * rnx * kx_scale[l + 32];

        float a0 = g_kvp[0][ba + l] + g_kvp[1][ba + l];
        float a1 = g_kvp[0][ba + l + 32] + g_kvp[1][ba + l + 32];
        float sa = a0 * a0 + a1 * a1;
        #pragma unroll
        for (int o = 16; o; o >>= 1) sa += __shfl_xor_sync(0xFFFFFFFFu, sa, o);
        float rna = 1.0f / fmaxf(sqrtf(sa), 1e-12f);
        float ka0 = a0 * rna * ka_scale[l];
        float ka1 = a1 * rna * ka_scale[l + 32];

        __half* pk = &g_Kh[(size_t)t * RD];
        pk[l]      = __float2half_rn(kx0 * c0 - ka0 * s0);
        pk[l + 64] = __float2half_rn(ka0 * c0 + kx0 * s0);
        pk[l + 32] = __float2half_rn(kx1 * c1 - ka1 * s1);
        pk[l + 96] = __float2half_rn(ka1 * c1 + kx1 * s1);
    } else {                // V (no norm, no rotary)
        size_t bx = (size_t)t * 128 + DH;
        size_t ba = (size_t)NT * 128 + bx;
        __half* pv = &g_Vh[(size_t)t * RD];
        pv[l]      = __float2half_rn(g_kvp[0][bx + l] + g_kvp[1][bx + l]);
        pv[l + 32] = __float2half_rn(g_kvp[0][bx + l + 32] + g_kvp[1][bx + l + 32]);
        pv[l + 64] = __float2half_rn(g_kvp[0][ba + l] + g_kvp[1][ba + l]);
        pv[l + 96] = __float2half_rn(g_kvp[0][ba + l + 32] + g_kvp[1][ba + l + 32]);
    }
}

// ---------------- tensor-core flash attention (fp16 mma, cp.async pipeline) -
// smem: sK[2][64][PADW] | sV[2][64][PADW] fp16 (Q staging aliases first 128 rows)
#define PADW 136
#define TILE_H (64 * PADW)   // halves per buffer

__device__ __forceinline__ uint32_t pack_f16(float lo, float hi) {
    __half2 p = __floats2half2_rn(lo, hi);
    return *reinterpret_cast<uint32_t*>(&p);
}

__global__ void __launch_bounds__(256) attn_mma_kernel(float* __restrict__ out) {
    extern __shared__ __half sm[];
    // buffers: sK0 @0, sK1 @TILE_H, sV0 @2*TILE_H, sV1 @3*TILE_H

    const int qb = blockIdx.x, h = blockIdx.y, b = blockIdx.z;
    const int tid = threadIdx.x, w = tid >> 5, lane = tid & 31;
    const int q0 = w * 16;

    // ---- stage Q tile (128x128 fp16) into smem (aliases sK0|sK1), preload a-frags
    const __half* Qg = g_Qh + (((size_t)b * HEADS + h) * NN + (size_t)qb * 128) * RD;
    for (int i = tid; i < 128 * 16; i += 256) {
        int r = i >> 4, c = i & 15;
        *reinterpret_cast<uint4*>(&sm[r * PADW + c * 8]) =
            *reinterpret_cast<const uint4*>(&Qg[r * RD + c * 8]);
    }
    __syncthreads();

    uint32_t qa[8][4];
    {
        uint32_t qbase = (uint32_t)__cvta_generic_to_shared(
            &sm[(q0 + (lane & 15)) * PADW + ((lane >> 4) << 3)]);
        #pragma unroll
        for (int ks = 0; ks < 8; ks++) {
            uint32_t addr = qbase + ks * 16 * 2;
            LDSM4(qa[ks][0], qa[ks][1], qa[ks][2], qa[ks][3], addr);
        }
    }
    __syncthreads();   // Q reads done; smem reusable for K/V

    float m_[2] = {-INFINITY, -INFINITY};
    float l_[2] = {0.0f, 0.0f};
    float o[16][4] = {};

    const __half* Kg = g_Kh + (size_t)b * NN * RD;
    const __half* Vg = g_Vh + (size_t)b * NN * RD;

    const uint32_t kbase0 = (uint32_t)__cvta_generic_to_shared(
        &sm[((lane & 7) + ((lane >> 4) << 3)) * PADW + (lane & 8)]);
    const uint32_t vbase0 = (uint32_t)__cvta_generic_to_shared(
        &sm[2 * TILE_H + (lane & 15) * PADW + ((lane >> 4) << 3)]);

    auto prefetch = [&](int kt, int buf) {
        const __half* Kt = Kg + (size_t)kt * 64 * RD;
        const __half* Vt = Vg + (size_t)kt * 64 * RD;
        __half* dK = sm + buf * TILE_H;
        __half* dV = sm + (2 + buf) * TILE_H;
        #pragma unroll
        for (int p = 0; p < 4; p++) {
            int idx = tid + p * 256;
            int r = idx >> 4, c8 = idx & 15;
            uint32_t dk = (uint32_t)__cvta_generic_to_shared(&dK[r * PADW + c8 * 8]);
            CP_ASYNC16(dk, Kt + (size_t)r * RD + c8 * 8);
            uint32_t dv = (uint32_t)__cvta_generic_to_shared(&dV[r * PADW + c8 * 8]);
            CP_ASYNC16(dv, Vt + (size_t)r * RD + c8 * 8);
        }
    };

    prefetch(0, 0);
    CP_COMMIT();

    for (int kt = 0; kt < NN / 64; kt++) {
        if (kt + 1 < NN / 64) {
            prefetch(kt + 1, (kt + 1) & 1);
            CP_COMMIT();
            asm volatile("cp.async.wait_group 1;\n");
        } else {
            asm volatile("cp.async.wait_group 0;\n");
        }
        __syncthreads();   // tile kt visible to all warps

        const uint32_t bufoff = (uint32_t)((kt & 1) * TILE_H * 2);  // bytes
        const uint32_t kbase = kbase0 + bufoff;
        const uint32_t vbase = vbase0 + bufoff;

        // ---- S = Q K^T  (S already in log2 units: Q pre-scaled by log2e/sqrt(128))
        float s[8][4] = {};
        #pragma unroll
        for (int ks = 0; ks < 8; ks++) {
            #pragma unroll
            for (int np = 0; np < 4; np++) {
                uint32_t addr = kbase + (uint32_t)((np * 16 * PADW + ks * 16) * 2);
                uint32_t b0, b1, b2, b3;
                LDSM4(b0, b1, b2, b3, addr);
                MMA16816(s[2 * np],     qa[ks], b0, b1);
                MMA16816(s[2 * np + 1], qa[ks], b2, b3);
            }
        }

        // ---- online softmax in registers (base-2)
        float mnew[2], alpha[2], lsum[2];
        #pragma unroll
        for (int r = 0; r < 2; r++) {
            float mx = m_[r];
            #pragma unroll
            for (int nt = 0; nt < 8; nt++)
                mx = fmaxf(mx, fmaxf(s[nt][2 * r], s[nt][2 * r + 1]));
            mx = fmaxf(mx, __shfl_xor_sync(0xFFFFFFFFu, mx, 1));
            mx = fmaxf(mx, __shfl_xor_sync(0xFFFFFFFFu, mx, 2));
            mnew[r] = mx;
            alpha[r] = exp2f(m_[r] - mx);
            lsum[r] = 0.0f;
        }
        #pragma unroll
        for (int nt = 0; nt < 8; nt++) {
            #pragma unroll
            for (int e = 0; e < 4; e++) {
                int r = e >> 1;
                float p = exp2f(s[nt][e] - mnew[r]);
                s[nt][e] = p;
                lsum[r] += p;
            }
        }
        #pragma unroll
        for (int r = 0; r < 2; r++) {
            lsum[r] += __shfl_xor_sync(0xFFFFFFFFu, lsum[r], 1);
            lsum[r] += __shfl_xor_sync(0xFFFFFFFFu, lsum[r], 2);
            l_[r] = l_[r] * alpha[r] + lsum[r];
            m_[r] = mnew[r];
        }
        #pragma unroll
        for (int j = 0; j < 16; j++) {
            o[j][0] *= alpha[0]; o[j][1] *= alpha[0];
            o[j][2] *= alpha[1]; o[j][3] *= alpha[1];
        }

        // ---- O += P V
        #pragma unroll
        for (int ks2 = 0; ks2 < 4; ks2++) {
            uint32_t pa[4];
            pa[0] = pack_f16(s[2 * ks2][0],     s[2 * ks2][1]);
            pa[1] = pack_f16(s[2 * ks2][2],     s[2 * ks2][3]);
            pa[2] = pack_f16(s[2 * ks2 + 1][0], s[2 * ks2 + 1][1]);
            pa[3] = pack_f16(s[2 * ks2 + 1][2], s[2 * ks2 + 1][3]);
            #pragma unroll
            for (int np = 0; np < 8; np++) {
                uint32_t addr = vbase + (uint32_t)((ks2 * 16 * PADW + np * 16) * 2);
                uint32_t v0, v1, v2, v3;
                LDSM4T(v0, v1, v2, v3, addr);
                MMA16816(o[2 * np],     pa, v0, v1);
                MMA16816(o[2 * np + 1], pa, v2, v3);
            }
        }
        __syncthreads();   // all warps done reading buf[kt&1] before kt+2 prefetch
    }

    // ---- normalize and store fp32: out[b][q][h*128+d]
    float rl0 = 1.0f / l_[0], rl1 = 1.0f / l_[1];
    int qrow = qb * 128 + q0 + (lane >> 2);
    #pragma unroll
    for (int j = 0; j < 16; j++) {
        int d = h * RD + j * 8 + 2 * (lane & 3);
        float* p0 = &out[((size_t)(b * NN + qrow)) * (HEADS * RD) + d];
        float* p1 = &out[((size_t)(b * NN + qrow + 8)) * (HEADS * RD) + d];
        *reinterpret_cast<float2*>(p0) = make_float2(o[j][0] * rl0, o[j][1] * rl0);
        *reinterpret_cast<float2*>(p1) = make_float2(o[j][2] * rl1, o[j][3] * rl1);
    }
}

// ---------------- launch ---------------------------------------------------
extern "C" void kernel_launch(void* const* d_in, const int* in_sizes, int n_in,
                              void* d_out, int out_size) {
    const float* x        = (const float*)d_in[0];
    const float* a        = (const float*)d_in[1];
    const float* Wq_x     = (const float*)d_in[2];
    const float* Wkv_x    = (const float*)d_in[3];
    const float* Wq_a     = (const float*)d_in[4];
    const float* Wkv_a    = (const float*)d_in[5];
    const float* qx_scale = (const float*)d_in[6];
    const float* qa_scale = (const float*)d_in[7];
    const float* kx_scale = (const float*)d_in[8];
    const float* ka_scale = (const float*)d_in[9];
    float* out = (float*)d_out;

    rope_invf_kernel<<<1, 64>>>();
    rope_table_kernel<<<(NN * DH + 255) / 256, 256>>>();

    // one launch: all split-precision expansions
    int expand_v4 = 2 * XV4 + 2 * WQV4 + 2 * WKV4;
    expand_all_kernel<<<(expand_v4 + 255) / 256, 256>>>(x, a, Wq_x, Wq_a, Wkv_x, Wkv_a);

    // one launch: all projections (Q 256 CTAs + KV split-K 64 CTAs)
    int proj_smem = (2 * SA_H + 2 * SB_H) * (int)sizeof(__half);  // 122880 B
    cudaFuncSetAttribute(proj_kernel, cudaFuncAttributeMaxDynamicSharedMemorySize, proj_smem);
    proj_kernel<<<320, 512, proj_smem>>>();

    prep_kernel<<<NT, 18 * 32>>>(qx_scale, qa_scale, kx_scale, ka_scale);

    int smem_bytes = 4 * TILE_H * (int)sizeof(__half);  // 69632 B
    cudaFuncSetAttribute(attn_mma_kernel, cudaFuncAttributeMaxDynamicSharedMemorySize, smem_bytes);
    attn_mma_kernel<<<dim3(NN / 128, HEADS, BB), 256, smem_bytes>>>(out);
}

// round 11
// speedup vs baseline: 7.2786x; 1.0505x over previous
#include <cuda_runtime.h>
#include <cuda_fp16.h>
#include <math.h>
#include <stdint.h>

#define BB 2
#define NN 2048
#define DIM 1024
#define HEADS 16
#define DH 64
#define RD 128
#define NT (BB*NN)
#define K3 3072           // expanded K for split-precision fp16 GEMM
#define NCHUNK (K3/32)    // 96

// ---------------- scratch (static device globals; no allocation) ------------
__device__ float g_qx[(size_t)NT*DIM];       // x @ Wq_x^T
__device__ float g_qa[(size_t)NT*DIM];       // a @ Wq_a^T
__device__ float g_kvx[(size_t)NT*2*DH];     // x @ Wkv_x^T
__device__ float g_kva[(size_t)NT*2*DH];     // a @ Wkv_a^T
__device__ __half g_Qh[(size_t)BB*HEADS*NN*RD]; // (b,h,n,128), pre-scaled log2e/sqrt(128)
__device__ __half g_Kh[(size_t)NT*RD];          // (b,n,128)
__device__ __half g_Vh[(size_t)NT*RD];          // (b,n,128)
__device__ float g_cos[NN*DH];
__device__ float g_sin[NN*DH];
__device__ float g_invf[DH];

// expanded split-precision operands (hi|lo|hi for X, hi|hi|lo for W)
__device__ __half g_xe[(size_t)NT*K3];
__device__ __half g_ae[(size_t)NT*K3];
__device__ __half g_wqxe[(size_t)DIM*K3];
__device__ __half g_wqae[(size_t)DIM*K3];
__device__ __half g_wkxe[(size_t)2*DH*K3];
__device__ __half g_wkae[(size_t)2*DH*K3];

// ---------------- RoPE tables ----------------------------------------------
__global__ void rope_invf_kernel() {
    int j = threadIdx.x;
    if (j < DH) g_invf[j] = (float)pow(10000.0, -(double)j / 64.0);
}

__global__ void rope_table_kernel() {
    int i = blockIdx.x * blockDim.x + threadIdx.x;
    if (i >= NN * DH) return;
    int n = i >> 6, j = i & 63;
    float ang = (float)n * g_invf[j];        // fp32 multiply, as the reference
    const float HI = 6.28318548202514648f;
    const float LO = -1.7484556e-7f;
    float k = rintf(ang * 0.15915494309189535f);
    float r = fmaf(-k, HI, ang);
    r = fmaf(-k, LO, r);                     // r in [-pi, pi], err ~2e-7
    g_cos[i] = cosf(r);
    g_sin[i] = sinf(r);
}

// ---------------- split-precision expansion (all 6 tensors, one launch) -----
// per-tensor: src [rows,1024] fp32 -> dst [rows,3072] fp16, 8 elems/thread
// wmode=0 (activations): [hi | lo | hi];  wmode=1 (weights): [hi | hi | lo]
#define XV8   (NT*DIM/8)       // 524288
#define WQV8  (DIM*DIM/8)      // 131072
#define WKV8  (2*DH*DIM/8)     // 16384

__device__ __forceinline__ void expand_one8(const float* __restrict__ src,
                                            __half* __restrict__ dst,
                                            int i8, int wmode) {
    int r = i8 >> 7, c = (i8 & 127) * 8;
    const float* s = &src[(size_t)r * 1024 + c];
    float4 v0 = *reinterpret_cast<const float4*>(s);
    float4 v1 = *reinterpret_cast<const float4*>(s + 4);
    __half2 h0 = __floats2half2_rn(v0.x, v0.y);
    __half2 h1 = __floats2half2_rn(v0.z, v0.w);
    __half2 h2 = __floats2half2_rn(v1.x, v1.y);
    __half2 h3 = __floats2half2_rn(v1.z, v1.w);
    __half2 l0 = __floats2half2_rn(v0.x - __half2float(__low2half(h0)),
                                   v0.y - __half2float(__high2half(h0)));
    __half2 l1 = __floats2half2_rn(v0.z - __half2float(__low2half(h1)),
                                   v0.w - __half2float(__high2half(h1)));
    __half2 l2 = __floats2half2_rn(v1.x - __half2float(__low2half(h2)),
                                   v1.y - __half2float(__high2half(h2)));
    __half2 l3 = __floats2half2_rn(v1.z - __half2float(__low2half(h3)),
                                   v1.w - __half2float(__high2half(h3)));
    __half* d = dst + (size_t)r * K3;
    uint4 hv = make_uint4(*reinterpret_cast<uint32_t*>(&h0), *reinterpret_cast<uint32_t*>(&h1),
                          *reinterpret_cast<uint32_t*>(&h2), *reinterpret_cast<uint32_t*>(&h3));
    uint4 lv = make_uint4(*reinterpret_cast<uint32_t*>(&l0), *reinterpret_cast<uint32_t*>(&l1),
                          *reinterpret_cast<uint32_t*>(&l2), *reinterpret_cast<uint32_t*>(&l3));
    *reinterpret_cast<uint4*>(&d[c]) = hv;
    if (wmode) {
        *reinterpret_cast<uint4*>(&d[c + 1024]) = hv;
        *reinterpret_cast<uint4*>(&d[c + 2048]) = lv;
    } else {
        *reinterpret_cast<uint4*>(&d[c + 1024]) = lv;
        *reinterpret_cast<uint4*>(&d[c + 2048]) = hv;
    }
}

__global__ void expand_all_kernel(const float* __restrict__ x, const float* __restrict__ a,
                                  const float* __restrict__ wqx, const float* __restrict__ wqa,
                                  const float* __restrict__ wkx, const float* __restrict__ wka) {
    int i = blockIdx.x * blockDim.x + threadIdx.x;
    if (i < XV8)  { expand_one8(x,   g_xe,   i, 0); return; }
    i -= XV8;
    if (i < XV8)  { expand_one8(a,   g_ae,   i, 0); return; }
    i -= XV8;
    if (i < WQV8) { expand_one8(wqx, g_wqxe, i, 1); return; }
    i -= WQV8;
    if (i < WQV8) { expand_one8(wqa, g_wqae, i, 1); return; }
    i -= WQV8;
    if (i < WKV8) { expand_one8(wkx, g_wkxe, i, 1); return; }
    i -= WKV8;
    if (i < WKV8) { expand_one8(wka, g_wkae, i, 1); }
}

// ---------------- MMA helpers ----------------------------------------------
#define LDSM4(R0,R1,R2,R3,ADDR) \
    asm volatile("ldmatrix.sync.aligned.m8n8.x4.shared.b16 {%0,%1,%2,%3}, [%4];" \
        : "=r"(R0),"=r"(R1),"=r"(R2),"=r"(R3) : "r"(ADDR))
#define LDSM4T(R0,R1,R2,R3,ADDR) \
    asm volatile("ldmatrix.sync.aligned.m8n8.x4.trans.shared.b16 {%0,%1,%2,%3}, [%4];" \
        : "=r"(R0),"=r"(R1),"=r"(R2),"=r"(R3) : "r"(ADDR))
#define MMA16816(C, A, B0, B1) \
    asm volatile("mma.sync.aligned.m16n8k16.row.col.f32.f16.f16.f32 " \
        "{%0,%1,%2,%3},{%4,%5,%6,%7},{%8,%9},{%0,%1,%2,%3};" \
        : "+f"((C)[0]),"+f"((C)[1]),"+f"((C)[2]),"+f"((C)[3]) \
        : "r"((A)[0]),"r"((A)[1]),"r"((A)[2]),"r"((A)[3]), "r"(B0),"r"(B1))
#define CP_ASYNC16(DST, SRC) \
    asm volatile("cp.async.cg.shared.global [%0], [%1], 16;\n" :: "r"(DST), "l"(SRC))
#define CP_COMMIT() asm volatile("cp.async.commit_group;\n")

// ---------------- unified projection GEMM: 128x128 tiles, 256 thr, 4 stages -
// Y[M,Nout] = A[M,K3] @ B[Nout,K3]^T, fp32 out.
// Grid: 512 Q-CTAs (2 which x 32m x 8n) + 64 KV-CTAs (2 which x 32m) = 576.
// 2 CTAs/SM (reg-capped), 4-stage cp.async pipeline.
#define GP 40   // smem row pitch in halves (32 data + 8 pad)
#define STG_H (128 * GP)        // halves per (A or B) stage
#define NSTAGE 4

__global__ void __launch_bounds__(256, 2) proj_kernel() {
    extern __shared__ __half ps[];
    __half* sA = ps;                    // [NSTAGE][128*GP]
    __half* sB = ps + NSTAGE * STG_H;   // [NSTAGE][128*GP]

    const int tid = threadIdx.x, lane = tid & 31, w = tid >> 5;
    const int wm = w & 3, wn = w >> 2;

    const __half* Ag; const __half* Bg; float* Y;
    int Nout, bm0, bn0;
    {
        int id = blockIdx.x;
        if (id < 512) {               // Q projections
            int which = id >> 8;
            int rem = id & 255;
            int mb = rem >> 3, nb = rem & 7;
            Ag = which ? g_ae : g_xe;
            Bg = which ? g_wqae : g_wqxe;
            Y  = which ? g_qa : g_qx;
            Nout = DIM; bm0 = mb * 128; bn0 = nb * 128;
        } else {                      // KV projections
            int id2 = id - 512;
            int which = id2 >> 5, mb = id2 & 31;
            Ag = which ? g_ae : g_xe;
            Bg = which ? g_wkae : g_wkxe;
            Y  = which ? g_kva : g_kvx;
            Nout = 128; bm0 = mb * 128; bn0 = 0;
        }
        Ag += (size_t)bm0 * K3;
        Bg += (size_t)bn0 * K3;
    }

    auto load_chunk = [&](int stg, int k0) {
        #pragma unroll
        for (int p = 0; p < 2; p++) {
            int idx = tid + p * 256;
            int row = idx >> 2, c8 = idx & 3;
            uint32_t da = (uint32_t)__cvta_generic_to_shared(&sA[stg * STG_H + row * GP + c8 * 8]);
            CP_ASYNC16(da, Ag + (size_t)row * K3 + k0 + c8 * 8);
            uint32_t db = (uint32_t)__cvta_generic_to_shared(&sB[stg * STG_H + row * GP + c8 * 8]);
            CP_ASYNC16(db, Bg + (size_t)row * K3 + k0 + c8 * 8);
        }
    };

    float c[2][8][4] = {};

    #pragma unroll
    for (int s = 0; s < NSTAGE - 1; s++) {
        load_chunk(s, s * 32);
        CP_COMMIT();
    }

    for (int ch = 0; ch < NCHUNK; ch++) {
        if (ch + NSTAGE - 1 < NCHUNK) {
            load_chunk((ch + NSTAGE - 1) & (NSTAGE - 1), (ch + NSTAGE - 1) * 32);
            CP_COMMIT();
            asm volatile("cp.async.wait_group %0;\n" :: "n"(NSTAGE - 1));
        } else {
            asm volatile("cp.async.wait_group 0;\n");
        }
        __syncthreads();
        const __half* cA = sA + (ch & (NSTAGE - 1)) * STG_H;
        const __half* cB = sB + (ch & (NSTAGE - 1)) * STG_H;
        #pragma unroll
        for (int kk = 0; kk < 2; kk++) {
            uint32_t a[2][4], bf[4][4];
            #pragma unroll
            for (int mt = 0; mt < 2; mt++) {
                uint32_t addr = (uint32_t)__cvta_generic_to_shared(
                    &cA[(wm * 32 + mt * 16 + (lane & 15)) * GP + ((lane >> 4) << 3) + kk * 16]);
                LDSM4(a[mt][0], a[mt][1], a[mt][2], a[mt][3], addr);
            }
            #pragma unroll
            for (int nt = 0; nt < 4; nt++) {
                uint32_t addr = (uint32_t)__cvta_generic_to_shared(
                    &cB[(wn * 64 + nt * 16 + ((lane & 7) + ((lane >> 4) << 3))) * GP + (lane & 8) + kk * 16]);
                LDSM4(bf[nt][0], bf[nt][1], bf[nt][2], bf[nt][3], addr);
            }
            #pragma unroll
            for (int mt = 0; mt < 2; mt++)
                #pragma unroll
                for (int nt = 0; nt < 4; nt++) {
                    MMA16816(c[mt][2 * nt],     a[mt], bf[nt][0], bf[nt][1]);
                    MMA16816(c[mt][2 * nt + 1], a[mt], bf[nt][2], bf[nt][3]);
                }
        }
        __syncthreads();
    }

    #pragma unroll
    for (int mt = 0; mt < 2; mt++) {
        int r0 = bm0 + wm * 32 + mt * 16 + (lane >> 2);
        #pragma unroll
        for (int n8 = 0; n8 < 8; n8++) {
            int col = bn0 + wn * 64 + n8 * 8 + 2 * (lane & 3);
            *reinterpret_cast<float2*>(&Y[(size_t)r0 * Nout + col]) =
                make_float2(c[mt][n8][0], c[mt][n8][1]);
            *reinterpret_cast<float2*>(&Y[(size_t)(r0 + 8) * Nout + col]) =
                make_float2(c[mt][n8][2], c[mt][n8][3]);
        }
    }
}

// ---------------- prep: l2norm + scale + concat + rotary -> fp16 -----------
// Q is additionally scaled by log2(e)/sqrt(128) so attention can use exp2.
__global__ void prep_kernel(const float* __restrict__ qx_scale,
                            const float* __restrict__ qa_scale,
                            const float* __restrict__ kx_scale,
                            const float* __restrict__ ka_scale) {
    int t = blockIdx.x;                 // global token 0..4095
    int b = t >> 11, n = t & (NN - 1);
    int w = threadIdx.x >> 5, l = threadIdx.x & 31;

    float c0 = g_cos[n * DH + l],      s0 = g_sin[n * DH + l];
    float c1 = g_cos[n * DH + l + 32], s1 = g_sin[n * DH + l + 32];
    const float SC = 0.08838834764831845f * 1.44269504088896341f; // log2e/sqrt(128)

    if (w < HEADS) {
        int h = w;
        const float* px = &g_qx[(size_t)t * DIM + h * DH];
        float x0 = px[l], x1 = px[l + 32];
        float sx = x0 * x0 + x1 * x1;
        #pragma unroll
        for (int o = 16; o; o >>= 1) sx += __shfl_xor_sync(0xFFFFFFFFu, sx, o);
        float rnx = 1.0f / fmaxf(sqrtf(sx), 1e-12f);
        float qx0 = x0 * rnx * qx_scale[h * DH + l];
        float qx1 = x1 * rnx * qx_scale[h * DH + l + 32];

        const float* pa = &g_qa[(size_t)t * DIM + h * DH];
        float a0 = pa[l], a1 = pa[l + 32];
        float sa = a0 * a0 + a1 * a1;
        #pragma unroll
        for (int o = 16; o; o >>= 1) sa += __shfl_xor_sync(0xFFFFFFFFu, sa, o);
        float rna = 1.0f / fmaxf(sqrtf(sa), 1e-12f);
        float qa0 = a0 * rna * qa_scale[h * DH + l];
        float qa1 = a1 * rna * qa_scale[h * DH + l + 32];

        __half* pq = &g_Qh[(((size_t)b * HEADS + h) * NN + n) * RD];
        pq[l]      = __float2half_rn(SC * (qx0 * c0 - qa0 * s0));
        pq[l + 64] = __float2half_rn(SC * (qa0 * c0 + qx0 * s0));
        pq[l + 32] = __float2half_rn(SC * (qx1 * c1 - qa1 * s1));
        pq[l + 96] = __float2half_rn(SC * (qa1 * c1 + qx1 * s1));
    } else if (w == 16) {   // K
        const float* px = &g_kvx[(size_t)t * 2 * DH];
        float x0 = px[l], x1 = px[l + 32];
        float sx = x0 * x0 + x1 * x1;
        #pragma unroll
        for (int o = 16; o; o >>= 1) sx += __shfl_xor_sync(0xFFFFFFFFu, sx, o);
        float rnx = 1.0f / fmaxf(sqrtf(sx), 1e-12f);
        float kx0 = x0 * rnx * kx_scale[l];
        float kx1 = x1 * rnx * kx_scale[l + 32];

        const float* pa = &g_kva[(size_t)t * 2 * DH];
        float a0 = pa[l], a1 = pa[l + 32];
        float sa = a0 * a0 + a1 * a1;
        #pragma unroll
        for (int o = 16; o; o >>= 1) sa += __shfl_xor_sync(0xFFFFFFFFu, sa, o);
        float rna = 1.0f / fmaxf(sqrtf(sa), 1e-12f);
        float ka0 = a0 * rna * ka_scale[l];
        float ka1 = a1 * rna * ka_scale[l + 32];

        __half* pk = &g_Kh[(size_t)t * RD];
        pk[l]      = __float2half_rn(kx0 * c0 - ka0 * s0);
        pk[l + 64] = __float2half_rn(ka0 * c0 + kx0 * s0);
        pk[l + 32] = __float2half_rn(kx1 * c1 - ka1 * s1);
        pk[l + 96] = __float2half_rn(ka1 * c1 + kx1 * s1);
    } else {                // V (no norm, no rotary)
        const float* px = &g_kvx[(size_t)t * 2 * DH + DH];
        const float* pa = &g_kva[(size_t)t * 2 * DH + DH];
        __half* pv = &g_Vh[(size_t)t * RD];
        pv[l]      = __float2half_rn(px[l]);
        pv[l + 32] = __float2half_rn(px[l + 32]);
        pv[l + 64] = __float2half_rn(pa[l]);
        pv[l + 96] = __float2half_rn(pa[l + 32]);
    }
}

// ---------------- tensor-core flash attention (fp16 mma, cp.async pipeline) -
// smem: sK[2][64][PADW] | sV[2][64][PADW] fp16 (Q staging aliases first 128 rows)
#define PADW 136
#define TILE_H (64 * PADW)   // halves per buffer

__device__ __forceinline__ uint32_t pack_f16(float lo, float hi) {
    __half2 p = __floats2half2_rn(lo, hi);
    return *reinterpret_cast<uint32_t*>(&p);
}

__global__ void __launch_bounds__(256) attn_mma_kernel(float* __restrict__ out) {
    extern __shared__ __half sm[];
    // buffers: sK0 @0, sK1 @TILE_H, sV0 @2*TILE_H, sV1 @3*TILE_H

    const int qb = blockIdx.x, h = blockIdx.y, b = blockIdx.z;
    const int tid = threadIdx.x, w = tid >> 5, lane = tid & 31;
    const int q0 = w * 16;

    // ---- stage Q tile (128x128 fp16) into smem (aliases sK0|sK1), preload a-frags
    const __half* Qg = g_Qh + (((size_t)b * HEADS + h) * NN + (size_t)qb * 128) * RD;
    for (int i = tid; i < 128 * 16; i += 256) {
        int r = i >> 4, c = i & 15;
        *reinterpret_cast<uint4*>(&sm[r * PADW + c * 8]) =
            *reinterpret_cast<const uint4*>(&Qg[r * RD + c * 8]);
    }
    __syncthreads();

    uint32_t qa[8][4];
    {
        uint32_t qbase = (uint32_t)__cvta_generic_to_shared(
            &sm[(q0 + (lane & 15)) * PADW + ((lane >> 4) << 3)]);
        #pragma unroll
        for (int ks = 0; ks < 8; ks++) {
            uint32_t addr = qbase + ks * 16 * 2;
            LDSM4(qa[ks][0], qa[ks][1], qa[ks][2], qa[ks][3], addr);
        }
    }
    __syncthreads();   // Q reads done; smem reusable for K/V

    float m_[2] = {-INFINITY, -INFINITY};
    float l_[2] = {0.0f, 0.0f};
    float o[16][4] = {};

    const __half* Kg = g_Kh + (size_t)b * NN * RD;
    const __half* Vg = g_Vh + (size_t)b * NN * RD;

    const uint32_t kbase0 = (uint32_t)__cvta_generic_to_shared(
        &sm[((lane & 7) + ((lane >> 4) << 3)) * PADW + (lane & 8)]);
    const uint32_t vbase0 = (uint32_t)__cvta_generic_to_shared(
        &sm[2 * TILE_H + (lane & 15) * PADW + ((lane >> 4) << 3)]);

    auto prefetch = [&](int kt, int buf) {
        const __half* Kt = Kg + (size_t)kt * 64 * RD;
        const __half* Vt = Vg + (size_t)kt * 64 * RD;
        __half* dK = sm + buf * TILE_H;
        __half* dV = sm + (2 + buf) * TILE_H;
        #pragma unroll
        for (int p = 0; p < 4; p++) {
            int idx = tid + p * 256;
            int r = idx >> 4, c8 = idx & 15;
            uint32_t dk = (uint32_t)__cvta_generic_to_shared(&dK[r * PADW + c8 * 8]);
            CP_ASYNC16(dk, Kt + (size_t)r * RD + c8 * 8);
            uint32_t dv = (uint32_t)__cvta_generic_to_shared(&dV[r * PADW + c8 * 8]);
            CP_ASYNC16(dv, Vt + (size_t)r * RD + c8 * 8);
        }
    };

    prefetch(0, 0);
    CP_COMMIT();

    for (int kt = 0; kt < NN / 64; kt++) {
        if (kt + 1 < NN / 64) {
            prefetch(kt + 1, (kt + 1) & 1);
            CP_COMMIT();
            asm volatile("cp.async.wait_group 1;\n");
        } else {
            asm volatile("cp.async.wait_group 0;\n");
        }
        __syncthreads();   // tile kt visible to all warps

        const uint32_t bufoff = (uint32_t)((kt & 1) * TILE_H * 2);  // bytes
        const uint32_t kbase = kbase0 + bufoff;
        const uint32_t vbase = vbase0 + bufoff;

        // ---- S = Q K^T  (S already in log2 units: Q pre-scaled by log2e/sqrt(128))
        float s[8][4] = {};
        #pragma unroll
        for (int ks = 0; ks < 8; ks++) {
            #pragma unroll
            for (int np = 0; np < 4; np++) {
                uint32_t addr = kbase + (uint32_t)((np * 16 * PADW + ks * 16) * 2);
                uint32_t b0, b1, b2, b3;
                LDSM4(b0, b1, b2, b3, addr);
                MMA16816(s[2 * np],     qa[ks], b0, b1);
                MMA16816(s[2 * np + 1], qa[ks], b2, b3);
            }
        }

        // ---- online softmax in registers (base-2)
        float mnew[2], alpha[2], lsum[2];
        #pragma unroll
        for (int r = 0; r < 2; r++) {
            float mx = m_[r];
            #pragma unroll
            for (int nt = 0; nt < 8; nt++)
                mx = fmaxf(mx, fmaxf(s[nt][2 * r], s[nt][2 * r + 1]));
            mx = fmaxf(mx, __shfl_xor_sync(0xFFFFFFFFu, mx, 1));
            mx = fmaxf(mx, __shfl_xor_sync(0xFFFFFFFFu, mx, 2));
            mnew[r] = mx;
            alpha[r] = exp2f(m_[r] - mx);
            lsum[r] = 0.0f;
        }
        #pragma unroll
        for (int nt = 0; nt < 8; nt++) {
            #pragma unroll
            for (int e = 0; e < 4; e++) {
                int r = e >> 1;
                float p = exp2f(s[nt][e] - mnew[r]);
                s[nt][e] = p;
                lsum[r] += p;
            }
        }
        #pragma unroll
        for (int r = 0; r < 2; r++) {
            lsum[r] += __shfl_xor_sync(0xFFFFFFFFu, lsum[r], 1);
            lsum[r] += __shfl_xor_sync(0xFFFFFFFFu, lsum[r], 2);
            l_[r] = l_[r] * alpha[r] + lsum[r];
            m_[r] = mnew[r];
        }
        #pragma unroll
        for (int j = 0; j < 16; j++) {
            o[j][0] *= alpha[0]; o[j][1] *= alpha[0];
            o[j][2] *= alpha[1]; o[j][3] *= alpha[1];
        }

        // ---- O += P V
        #pragma unroll
        for (int ks2 = 0; ks2 < 4; ks2++) {
            uint32_t pa[4];
            pa[0] = pack_f16(s[2 * ks2][0],     s[2 * ks2][1]);
            pa[1] = pack_f16(s[2 * ks2][2],     s[2 * ks2][3]);
            pa[2] = pack_f16(s[2 * ks2 + 1][0], s[2 * ks2 + 1][1]);
            pa[3] = pack_f16(s[2 * ks2 + 1][2], s[2 * ks2 + 1][3]);
            #pragma unroll
            for (int np = 0; np < 8; np++) {
                uint32_t addr = vbase + (uint32_t)((ks2 * 16 * PADW + np * 16) * 2);
                uint32_t v0, v1, v2, v3;
                LDSM4T(v0, v1, v2, v3, addr);
                MMA16816(o[2 * np],     pa, v0, v1);
                MMA16816(o[2 * np + 1], pa, v2, v3);
            }
        }
        __syncthreads();   // all warps done reading buf[kt&1] before kt+2 prefetch
    }

    // ---- normalize and store fp32: out[b][q][h*128+d]
    float rl0 = 1.0f / l_[0], rl1 = 1.0f / l_[1];
    int qrow = qb * 128 + q0 + (lane >> 2);
    #pragma unroll
    for (int j = 0; j < 16; j++) {
        int d = h * RD + j * 8 + 2 * (lane & 3);
        float* p0 = &out[((size_t)(b * NN + qrow)) * (HEADS * RD) + d];
        float* p1 = &out[((size_t)(b * NN + qrow + 8)) * (HEADS * RD) + d];
        *reinterpret_cast<float2*>(p0) = make_float2(o[j][0] * rl0, o[j][1] * rl0);
        *reinterpret_cast<float2*>(p1) = make_float2(o[j][2] * rl1, o[j][3] * rl1);
    }
}

// ---------------- launch ---------------------------------------------------
extern "C" void kernel_launch(void* const* d_in, const int* in_sizes, int n_in,
                              void* d_out, int out_size) {
    const float* x        = (const float*)d_in[0];
    const float* a        = (const float*)d_in[1];
    const float* Wq_x     = (const float*)d_in[2];
    const float* Wkv_x    = (const float*)d_in[3];
    const float* Wq_a     = (const float*)d_in[4];
    const float* Wkv_a    = (const float*)d_in[5];
    const float* qx_scale = (const float*)d_in[6];
    const float* qa_scale = (const float*)d_in[7];
    const float* kx_scale = (const float*)d_in[8];
    const float* ka_scale = (const float*)d_in[9];
    float* out = (float*)d_out;

    rope_invf_kernel<<<1, 64>>>();
    rope_table_kernel<<<(NN * DH + 255) / 256, 256>>>();

    // one launch: all split-precision expansions (8 elems/thread)
    int expand_v8 = 2 * XV8 + 2 * WQV8 + 2 * WKV8;
    expand_all_kernel<<<(expand_v8 + 255) / 256, 256>>>(x, a, Wq_x, Wq_a, Wkv_x, Wkv_a);

    // one launch: all projections (512 Q-CTAs + 64 KV-CTAs, 2 CTAs/SM)
    int proj_smem = 2 * NSTAGE * STG_H * (int)sizeof(__half);  // 81920 B
    cudaFuncSetAttribute(proj_kernel, cudaFuncAttributeMaxDynamicSharedMemorySize, proj_smem);
    proj_kernel<<<576, 256, proj_smem>>>();

    prep_kernel<<<NT, 18 * 32>>>(qx_scale, qa_scale, kx_scale, ka_scale);

    int smem_bytes = 4 * TILE_H * (int)sizeof(__half);  // 69632 B
    cudaFuncSetAttribute(attn_mma_kernel, cudaFuncAttributeMaxDynamicSharedMemorySize, smem_bytes);
    attn_mma_kernel<<<dim3(NN / 128, HEADS, BB), 256, smem_bytes>>>(out);
}

// round 13
// speedup vs baseline: 9.3371x; 1.2828x over previous
#include <cuda_runtime.h>
#include <cuda_fp16.h>
#include <math.h>
#include <stdint.h>

#define BB 2
#define NN 2048
#define DIM 1024
#define HEADS 16
#define DH 64
#define RD 128
#define NT (BB*NN)
#define K2 2048            // expanded K: [hi | lo] for X, [hi | hi] for W
#define NCH_Q 32           // Q proj: hi-only, K=1024, 32h chunks
#define NCH_KV 64          // KV proj: 2-pass, K=2048

// ---------------- scratch (static device globals; no allocation) ------------
__device__ float g_qx[(size_t)NT*DIM];       // x @ Wq_x^T
__device__ float g_qa[(size_t)NT*DIM];       // a @ Wq_a^T
__device__ float g_kvx[(size_t)NT*2*DH];     // x @ Wkv_x^T
__device__ float g_kva[(size_t)NT*2*DH];     // a @ Wkv_a^T
__device__ __half g_Qh[(size_t)BB*HEADS*NN*RD]; // pre-scaled log2e/sqrt(128)
__device__ __half g_Kh[(size_t)NT*RD];
__device__ __half g_Vh[(size_t)NT*RD];
__device__ float g_cos[NN*DH];
__device__ float g_sin[NN*DH];
__device__ float g_invf[DH];

// expanded split-precision operands: X -> [hi | lo], W -> [hi | hi]
__device__ __half g_xe[(size_t)NT*K2];
__device__ __half g_ae[(size_t)NT*K2];
__device__ __half g_wqxe[(size_t)DIM*K2];
__device__ __half g_wqae[(size_t)DIM*K2];
__device__ __half g_wkxe[(size_t)2*DH*K2];
__device__ __half g_wkae[(size_t)2*DH*K2];

// ---------------- RoPE tables ----------------------------------------------
__global__ void rope_invf_kernel() {
    int j = threadIdx.x;
    if (j < DH) g_invf[j] = (float)pow(10000.0, -(double)j / 64.0);
}

__global__ void rope_table_kernel() {
    int i = blockIdx.x * blockDim.x + threadIdx.x;
    if (i >= NN * DH) return;
    int n = i >> 6, j = i & 63;
    float ang = (float)n * g_invf[j];        // fp32 multiply, as the reference
    const float HI = 6.28318548202514648f;
    const float LO = -1.7484556e-7f;
    float k = rintf(ang * 0.15915494309189535f);
    float r = fmaf(-k, HI, ang);
    r = fmaf(-k, LO, r);                     // r in [-pi, pi], err ~2e-7
    g_cos[i] = cosf(r);
    g_sin[i] = sinf(r);
}

// ---------------- split-precision expansion (all 6 tensors, one launch) -----
// per-tensor: src [rows,1024] fp32 -> dst [rows,2048] fp16, 8 elems/thread
// wmode=0 (activations): [hi | lo];  wmode=1 (weights): [hi | hi]
#define XV8   (NT*DIM/8)       // 524288
#define WQV8  (DIM*DIM/8)      // 131072
#define WKV8  (2*DH*DIM/8)     // 16384

__device__ __forceinline__ void expand_one8(const float* __restrict__ src,
                                            __half* __restrict__ dst,
                                            int i8, int wmode) {
    int r = i8 >> 7, c = (i8 & 127) * 8;
    const float* s = &src[(size_t)r * 1024 + c];
    float4 v0 = *reinterpret_cast<const float4*>(s);
    float4 v1 = *reinterpret_cast<const float4*>(s + 4);
    __half2 h0 = __floats2half2_rn(v0.x, v0.y);
    __half2 h1 = __floats2half2_rn(v0.z, v0.w);
    __half2 h2 = __floats2half2_rn(v1.x, v1.y);
    __half2 h3 = __floats2half2_rn(v1.z, v1.w);
    __half* d = dst + (size_t)r * K2;
    uint4 hv = make_uint4(*reinterpret_cast<uint32_t*>(&h0), *reinterpret_cast<uint32_t*>(&h1),
                          *reinterpret_cast<uint32_t*>(&h2), *reinterpret_cast<uint32_t*>(&h3));
    *reinterpret_cast<uint4*>(&d[c]) = hv;
    if (wmode) {
        *reinterpret_cast<uint4*>(&d[c + 1024]) = hv;
    } else {
        __half2 l0 = __floats2half2_rn(v0.x - __half2float(__low2half(h0)),
                                       v0.y - __half2float(__high2half(h0)));
        __half2 l1 = __floats2half2_rn(v0.z - __half2float(__low2half(h1)),
                                       v0.w - __half2float(__high2half(h1)));
        __half2 l2 = __floats2half2_rn(v1.x - __half2float(__low2half(h2)),
                                       v1.y - __half2float(__high2half(h2)));
        __half2 l3 = __floats2half2_rn(v1.z - __half2float(__low2half(h3)),
                                       v1.w - __half2float(__high2half(h3)));
        uint4 lv = make_uint4(*reinterpret_cast<uint32_t*>(&l0), *reinterpret_cast<uint32_t*>(&l1),
                              *reinterpret_cast<uint32_t*>(&l2), *reinterpret_cast<uint32_t*>(&l3));
        *reinterpret_cast<uint4*>(&d[c + 1024]) = lv;
    }
}

__global__ void expand_all_kernel(const float* __restrict__ x, const float* __restrict__ a,
                                  const float* __restrict__ wqx, const float* __restrict__ wqa,
                                  const float* __restrict__ wkx, const float* __restrict__ wka) {
    int i = blockIdx.x * blockDim.x + threadIdx.x;
    if (i < XV8)  { expand_one8(x,   g_xe,   i, 0); return; }
    i -= XV8;
    if (i < XV8)  { expand_one8(a,   g_ae,   i, 0); return; }
    i -= XV8;
    if (i < WQV8) { expand_one8(wqx, g_wqxe, i, 1); return; }
    i -= WQV8;
    if (i < WQV8) { expand_one8(wqa, g_wqae, i, 1); return; }
    i -= WQV8;
    if (i < WKV8) { expand_one8(wkx, g_wkxe, i, 1); return; }
    i -= WKV8;
    if (i < WKV8) { expand_one8(wka, g_wkae, i, 1); }
}

// ---------------- MMA helpers ----------------------------------------------
#define LDSM4(R0,R1,R2,R3,ADDR) \
    asm volatile("ldmatrix.sync.aligned.m8n8.x4.shared.b16 {%0,%1,%2,%3}, [%4];" \
        : "=r"(R0),"=r"(R1),"=r"(R2),"=r"(R3) : "r"(ADDR))
#define LDSM4T(R0,R1,R2,R3,ADDR) \
    asm volatile("ldmatrix.sync.aligned.m8n8.x4.trans.shared.b16 {%0,%1,%2,%3}, [%4];" \
        : "=r"(R0),"=r"(R1),"=r"(R2),"=r"(R3) : "r"(ADDR))
#define MMA16816(C, A, B0, B1) \
    asm volatile("mma.sync.aligned.m16n8k16.row.col.f32.f16.f16.f32 " \
        "{%0,%1,%2,%3},{%4,%5,%6,%7},{%8,%9},{%0,%1,%2,%3};" \
        : "+f"((C)[0]),"+f"((C)[1]),"+f"((C)[2]),"+f"((C)[3]) \
        : "r"((A)[0]),"r"((A)[1]),"r"((A)[2]),"r"((A)[3]), "r"(B0),"r"(B1))
#define CP_ASYNC16(DST, SRC) \
    asm volatile("cp.async.cg.shared.global [%0], [%1], 16;\n" :: "r"(DST), "l"(SRC))
#define CP_COMMIT() asm volatile("cp.async.commit_group;\n")

// ---------------- unified projection GEMM: 128x128 tiles, 256 thr, 4 stages -
// Y[M,Nout] = A[M,*] @ B[Nout,*]^T, fp32 out.
// Grid: 512 Q-CTAs (hi-only K=1024) + 64 KV-CTAs (2-pass K=2048) = 576.
// 2 CTAs/SM (reg-capped), 4-stage cp.async pipeline, 32h chunks.
#define GP 40   // smem row pitch in halves (32 data + 8 pad)
#define STG_H (128 * GP)        // halves per (A or B) stage
#define NSTAGE 4

__global__ void __launch_bounds__(256, 2) proj_kernel() {
    extern __shared__ __half ps[];
    __half* sA = ps;                    // [NSTAGE][128*GP]
    __half* sB = ps + NSTAGE * STG_H;   // [NSTAGE][128*GP]

    const int tid = threadIdx.x, lane = tid & 31, w = tid >> 5;
    const int wm = w & 3, wn = w >> 2;

    const __half* Ag; const __half* Bg; float* Y;
    int Nout, bm0, bn0, nch;
    {
        int id = blockIdx.x;
        if (id < 512) {               // Q projections: hi-only (first 1024 K)
            int which = id >> 8;
            int rem = id & 255;
            int mb = rem >> 3, nb = rem & 7;
            Ag = which ? g_ae : g_xe;
            Bg = which ? g_wqae : g_wqxe;
            Y  = which ? g_qa : g_qx;
            Nout = DIM; bm0 = mb * 128; bn0 = nb * 128;
            nch = NCH_Q;
        } else {                      // KV projections: full 2-pass K=2048
            int id2 = id - 512;
            int which = id2 >> 5, mb = id2 & 31;
            Ag = which ? g_ae : g_xe;
            Bg = which ? g_wkae : g_wkxe;
            Y  = which ? g_kva : g_kvx;
            Nout = 128; bm0 = mb * 128; bn0 = 0;
            nch = NCH_KV;
        }
        Ag += (size_t)bm0 * K2;
        Bg += (size_t)bn0 * K2;
    }

    auto load_chunk = [&](int stg, int k0) {
        #pragma unroll
        for (int p = 0; p < 2; p++) {
            int idx = tid + p * 256;
            int row = idx >> 2, c8 = idx & 3;
            uint32_t da = (uint32_t)__cvta_generic_to_shared(&sA[stg * STG_H + row * GP + c8 * 8]);
            CP_ASYNC16(da, Ag + (size_t)row * K2 + k0 + c8 * 8);
            uint32_t db = (uint32_t)__cvta_generic_to_shared(&sB[stg * STG_H + row * GP + c8 * 8]);
            CP_ASYNC16(db, Bg + (size_t)row * K2 + k0 + c8 * 8);
        }
    };

    float c[2][8][4] = {};

    #pragma unroll
    for (int s = 0; s < NSTAGE - 1; s++) {
        load_chunk(s, s * 32);
        CP_COMMIT();
    }

    for (int ch = 0; ch < nch; ch++) {
        if (ch + NSTAGE - 1 < nch) {
            load_chunk((ch + NSTAGE - 1) & (NSTAGE - 1), (ch + NSTAGE - 1) * 32);
            CP_COMMIT();
            asm volatile("cp.async.wait_group %0;\n" :: "n"(NSTAGE - 1));
        } else {
            asm volatile("cp.async.wait_group 0;\n");
        }
        __syncthreads();
        const __half* cA = sA + (ch & (NSTAGE - 1)) * STG_H;
        const __half* cB = sB + (ch & (NSTAGE - 1)) * STG_H;
        #pragma unroll
        for (int kk = 0; kk < 2; kk++) {
            uint32_t a[2][4], bf[4][4];
            #pragma unroll
            for (int mt = 0; mt < 2; mt++) {
                uint32_t addr = (uint32_t)__cvta_generic_to_shared(
                    &cA[(wm * 32 + mt * 16 + (lane & 15)) * GP + ((lane >> 4) << 3) + kk * 16]);
                LDSM4(a[mt][0], a[mt][1], a[mt][2], a[mt][3], addr);
            }
            #pragma unroll
            for (int nt = 0; nt < 4; nt++) {
                uint32_t addr = (uint32_t)__cvta_generic_to_shared(
                    &cB[(wn * 64 + nt * 16 + ((lane & 7) + ((lane >> 4) << 3))) * GP + (lane & 8) + kk * 16]);
                LDSM4(bf[nt][0], bf[nt][1], bf[nt][2], bf[nt][3], addr);
            }
            #pragma unroll
            for (int mt = 0; mt < 2; mt++)
                #pragma unroll
                for (int nt = 0; nt < 4; nt++) {
                    MMA16816(c[mt][2 * nt],     a[mt], bf[nt][0], bf[nt][1]);
                    MMA16816(c[mt][2 * nt + 1], a[mt], bf[nt][2], bf[nt][3]);
                }
        }
        __syncthreads();
    }

    #pragma unroll
    for (int mt = 0; mt < 2; mt++) {
        int r0 = bm0 + wm * 32 + mt * 16 + (lane >> 2);
        #pragma unroll
        for (int n8 = 0; n8 < 8; n8++) {
            int col = bn0 + wn * 64 + n8 * 8 + 2 * (lane & 3);
            *reinterpret_cast<float2*>(&Y[(size_t)r0 * Nout + col]) =
                make_float2(c[mt][n8][0], c[mt][n8][1]);
            *reinterpret_cast<float2*>(&Y[(size_t)(r0 + 8) * Nout + col]) =
                make_float2(c[mt][n8][2], c[mt][n8][3]);
        }
    }
}

// ---------------- prep: l2norm + scale + concat + rotary -> fp16 -----------
// Q is additionally scaled by log2(e)/sqrt(128) so attention can use exp2.
__global__ void prep_kernel(const float* __restrict__ qx_scale,
                            const float* __restrict__ qa_scale,
                            const float* __restrict__ kx_scale,
                            const float* __restrict__ ka_scale) {
    int t = blockIdx.x;                 // global token 0..4095
    int b = t >> 11, n = t & (NN - 1);
    int w = threadIdx.x >> 5, l = threadIdx.x & 31;

    float c0 = g_cos[n * DH + l],      s0 = g_sin[n * DH + l];
    float c1 = g_cos[n * DH + l + 32], s1 = g_sin[n * DH + l + 32];
    const float SC = 0.08838834764831845f * 1.44269504088896341f; // log2e/sqrt(128)

    if (w < HEADS) {
        int h = w;
        const float* px = &g_qx[(size_t)t * DIM + h * DH];
        float x0 = px[l], x1 = px[l + 32];
        float sx = x0 * x0 + x1 * x1;
        #pragma unroll
        for (int o = 16; o; o >>= 1) sx += __shfl_xor_sync(0xFFFFFFFFu, sx, o);
        float rnx = 1.0f / fmaxf(sqrtf(sx), 1e-12f);
        float qx0 = x0 * rnx * qx_scale[h * DH + l];
        float qx1 = x1 * rnx * qx_scale[h * DH + l + 32];

        const float* pa = &g_qa[(size_t)t * DIM + h * DH];
        float a0 = pa[l], a1 = pa[l + 32];
        float sa = a0 * a0 + a1 * a1;
        #pragma unroll
        for (int o = 16; o; o >>= 1) sa += __shfl_xor_sync(0xFFFFFFFFu, sa, o);
        float rna = 1.0f / fmaxf(sqrtf(sa), 1e-12f);
        float qa0 = a0 * rna * qa_scale[h * DH + l];
        float qa1 = a1 * rna * qa_scale[h * DH + l + 32];

        __half* pq = &g_Qh[(((size_t)b * HEADS + h) * NN + n) * RD];
        pq[l]      = __float2half_rn(SC * (qx0 * c0 - qa0 * s0));
        pq[l + 64] = __float2half_rn(SC * (qa0 * c0 + qx0 * s0));
        pq[l + 32] = __float2half_rn(SC * (qx1 * c1 - qa1 * s1));
        pq[l + 96] = __float2half_rn(SC * (qa1 * c1 + qx1 * s1));
    } else if (w == 16) {   // K
        const float* px = &g_kvx[(size_t)t * 2 * DH];
        float x0 = px[l], x1 = px[l + 32];
        float sx = x0 * x0 + x1 * x1;
        #pragma unroll
        for (int o = 16; o; o >>= 1) sx += __shfl_xor_sync(0xFFFFFFFFu, sx, o);
        float rnx = 1.0f / fmaxf(sqrtf(sx), 1e-12f);
        float kx0 = x0 * rnx * kx_scale[l];
        float kx1 = x1 * rnx * kx_scale[l + 32];

        const float* pa = &g_kva[(size_t)t * 2 * DH];
        float a0 = pa[l], a1 = pa[l + 32];
        float sa = a0 * a0 + a1 * a1;
        #pragma unroll
        for (int o = 16; o; o >>= 1) sa += __shfl_xor_sync(0xFFFFFFFFu, sa, o);
        float rna = 1.0f / fmaxf(sqrtf(sa), 1e-12f);
        float ka0 = a0 * rna * ka_scale[l];
        float ka1 = a1 * rna * ka_scale[l + 32];

        __half* pk = &g_Kh[(size_t)t * RD];
        pk[l]      = __float2half_rn(kx0 * c0 - ka0 * s0);
        pk[l + 64] = __float2half_rn(ka0 * c0 + kx0 * s0);
        pk[l + 32] = __float2half_rn(kx1 * c1 - ka1 * s1);
        pk[l + 96] = __float2half_rn(ka1 * c1 + kx1 * s1);
    } else {                // V (no norm, no rotary)
        const float* px = &g_kvx[(size_t)t * 2 * DH + DH];
        const float* pa = &g_kva[(size_t)t * 2 * DH + DH];
        __half* pv = &g_Vh[(size_t)t * RD];
        pv[l]      = __float2half_rn(px[l]);
        pv[l + 32] = __float2half_rn(px[l + 32]);
        pv[l + 64] = __float2half_rn(pa[l]);
        pv[l + 96] = __float2half_rn(pa[l + 32]);
    }
}

// ---------------- tensor-core flash attention (fp16 mma, cp.async pipeline) -
#define PADW 136
#define TILE_H (64 * PADW)   // halves per buffer

__device__ __forceinline__ uint32_t pack_f16(float lo, float hi) {
    __half2 p = __floats2half2_rn(lo, hi);
    return *reinterpret_cast<uint32_t*>(&p);
}

__global__ void __launch_bounds__(256) attn_mma_kernel(float* __restrict__ out) {
    extern __shared__ __half sm[];
    // buffers: sK0 @0, sK1 @TILE_H, sV0 @2*TILE_H, sV1 @3*TILE_H

    const int qb = blockIdx.x, h = blockIdx.y, b = blockIdx.z;
    const int tid = threadIdx.x, w = tid >> 5, lane = tid & 31;
    const int q0 = w * 16;

    // ---- stage Q tile (128x128 fp16) into smem (aliases sK0|sK1), preload a-frags
    const __half* Qg = g_Qh + (((size_t)b * HEADS + h) * NN + (size_t)qb * 128) * RD;
    for (int i = tid; i < 128 * 16; i += 256) {
        int r = i >> 4, c = i & 15;
        *reinterpret_cast<uint4*>(&sm[r * PADW + c * 8]) =
            *reinterpret_cast<const uint4*>(&Qg[r * RD + c * 8]);
    }
    __syncthreads();

    uint32_t qa[8][4];
    {
        uint32_t qbase = (uint32_t)__cvta_generic_to_shared(
            &sm[(q0 + (lane & 15)) * PADW + ((lane >> 4) << 3)]);
        #pragma unroll
        for (int ks = 0; ks < 8; ks++) {
            uint32_t addr = qbase + ks * 16 * 2;
            LDSM4(qa[ks][0], qa[ks][1], qa[ks][2], qa[ks][3], addr);
        }
    }
    __syncthreads();   // Q reads done; smem reusable for K/V

    float m_[2] = {-INFINITY, -INFINITY};
    float l_[2] = {0.0f, 0.0f};
    float o[16][4] = {};

    const __half* Kg = g_Kh + (size_t)b * NN * RD;
    const __half* Vg = g_Vh + (size_t)b * NN * RD;

    const uint32_t kbase0 = (uint32_t)__cvta_generic_to_shared(
        &sm[((lane & 7) + ((lane >> 4) << 3)) * PADW + (lane & 8)]);
    const uint32_t vbase0 = (uint32_t)__cvta_generic_to_shared(
        &sm[2 * TILE_H + (lane & 15) * PADW + ((lane >> 4) << 3)]);

    auto prefetch = [&](int kt, int buf) {
        const __half* Kt = Kg + (size_t)kt * 64 * RD;
        const __half* Vt = Vg + (size_t)kt * 64 * RD;
        __half* dK = sm + buf * TILE_H;
        __half* dV = sm + (2 + buf) * TILE_H;
        #pragma unroll
        for (int p = 0; p < 4; p++) {
            int idx = tid + p * 256;
            int r = idx >> 4, c8 = idx & 15;
            uint32_t dk = (uint32_t)__cvta_generic_to_shared(&dK[r * PADW + c8 * 8]);
            CP_ASYNC16(dk, Kt + (size_t)r * RD + c8 * 8);
            uint32_t dv = (uint32_t)__cvta_generic_to_shared(&dV[r * PADW + c8 * 8]);
            CP_ASYNC16(dv, Vt + (size_t)r * RD + c8 * 8);
        }
    };

    prefetch(0, 0);
    CP_COMMIT();

    for (int kt = 0; kt < NN / 64; kt++) {
        if (kt + 1 < NN / 64) {
            prefetch(kt + 1, (kt + 1) & 1);
            CP_COMMIT();
            asm volatile("cp.async.wait_group 1;\n");
        } else {
            asm volatile("cp.async.wait_group 0;\n");
        }
        __syncthreads();   // tile kt visible to all warps

        const uint32_t bufoff = (uint32_t)((kt & 1) * TILE_H * 2);  // bytes
        const uint32_t kbase = kbase0 + bufoff;
        const uint32_t vbase = vbase0 + bufoff;

        // ---- S = Q K^T  (S in log2 units)
        float s[8][4] = {};
        #pragma unroll
        for (int ks = 0; ks < 8; ks++) {
            #pragma unroll
            for (int np = 0; np < 4; np++) {
                uint32_t addr = kbase + (uint32_t)((np * 16 * PADW + ks * 16) * 2);
                uint32_t b0, b1, b2, b3;
                LDSM4(b0, b1, b2, b3, addr);
                MMA16816(s[2 * np],     qa[ks], b0, b1);
                MMA16816(s[2 * np + 1], qa[ks], b2, b3);
            }
        }

        // ---- online softmax in registers (base-2)
        float mnew[2], alpha[2], lsum[2];
        #pragma unroll
        for (int r = 0; r < 2; r++) {
            float mx = m_[r];
            #pragma unroll
            for (int nt = 0; nt < 8; nt++)
                mx = fmaxf(mx, fmaxf(s[nt][2 * r], s[nt][2 * r + 1]));
            mx = fmaxf(mx, __shfl_xor_sync(0xFFFFFFFFu, mx, 1));
            mx = fmaxf(mx, __shfl_xor_sync(0xFFFFFFFFu, mx, 2));
            mnew[r] = mx;
            alpha[r] = exp2f(m_[r] - mx);
            lsum[r] = 0.0f;
        }
        #pragma unroll
        for (int nt = 0; nt < 8; nt++) {
            #pragma unroll
            for (int e = 0; e < 4; e++) {
                int r = e >> 1;
                float p = exp2f(s[nt][e] - mnew[r]);
                s[nt][e] = p;
                lsum[r] += p;
            }
        }
        #pragma unroll
        for (int r = 0; r < 2; r++) {
            lsum[r] += __shfl_xor_sync(0xFFFFFFFFu, lsum[r], 1);
            lsum[r] += __shfl_xor_sync(0xFFFFFFFFu, lsum[r], 2);
            l_[r] = l_[r] * alpha[r] + lsum[r];
            m_[r] = mnew[r];
        }
        #pragma unroll
        for (int j = 0; j < 16; j++) {
            o[j][0] *= alpha[0]; o[j][1] *= alpha[0];
            o[j][2] *= alpha[1]; o[j][3] *= alpha[1];
        }

        // ---- O += P V
        #pragma unroll
        for (int ks2 = 0; ks2 < 4; ks2++) {
            uint32_t pa[4];
            pa[0] = pack_f16(s[2 * ks2][0],     s[2 * ks2][1]);
            pa[1] = pack_f16(s[2 * ks2][2],     s[2 * ks2][3]);
            pa[2] = pack_f16(s[2 * ks2 + 1][0], s[2 * ks2 + 1][1]);
            pa[3] = pack_f16(s[2 * ks2 + 1][2], s[2 * ks2 + 1][3]);
            #pragma unroll
            for (int np = 0; np < 8; np++) {
                uint32_t addr = vbase + (uint32_t)((ks2 * 16 * PADW + np * 16) * 2);
                uint32_t v0, v1, v2, v3;
                LDSM4T(v0, v1, v2, v3, addr);
                MMA16816(o[2 * np],     pa, v0, v1);
                MMA16816(o[2 * np + 1], pa, v2, v3);
            }
        }
        __syncthreads();   // all warps done reading buf[kt&1] before kt+2 prefetch
    }

    // ---- normalize and store fp32: out[b][q][h*128+d]
    float rl0 = 1.0f / l_[0], rl1 = 1.0f / l_[1];
    int qrow = qb * 128 + q0 + (lane >> 2);
    #pragma unroll
    for (int j = 0; j < 16; j++) {
        int d = h * RD + j * 8 + 2 * (lane & 3);
        float* p0 = &out[((size_t)(b * NN + qrow)) * (HEADS * RD) + d];
        float* p1 = &out[((size_t)(b * NN + qrow + 8)) * (HEADS * RD) + d];
        *reinterpret_cast<float2*>(p0) = make_float2(o[j][0] * rl0, o[j][1] * rl0);
        *reinterpret_cast<float2*>(p1) = make_float2(o[j][2] * rl1, o[j][3] * rl1);
    }
}

// ---------------- launch ---------------------------------------------------
extern "C" void kernel_launch(void* const* d_in, const int* in_sizes, int n_in,
                              void* d_out, int out_size) {
    const float* x        = (const float*)d_in[0];
    const float* a        = (const float*)d_in[1];
    const float* Wq_x     = (const float*)d_in[2];
    const float* Wkv_x    = (const float*)d_in[3];
    const float* Wq_a     = (const float*)d_in[4];
    const float* Wkv_a    = (const float*)d_in[5];
    const float* qx_scale = (const float*)d_in[6];
    const float* qa_scale = (const float*)d_in[7];
    const float* kx_scale = (const float*)d_in[8];
    const float* ka_scale = (const float*)d_in[9];
    float* out = (float*)d_out;

    rope_invf_kernel<<<1, 64>>>();
    rope_table_kernel<<<(NN * DH + 255) / 256, 256>>>();

    // one launch: all split-precision expansions (8 elems/thread, 2-pass)
    int expand_v8 = 2 * XV8 + 2 * WQV8 + 2 * WKV8;
    expand_all_kernel<<<(expand_v8 + 255) / 256, 256>>>(x, a, Wq_x, Wq_a, Wkv_x, Wkv_a);

    // one launch: all projections (512 Q hi-only + 64 KV 2-pass, 2 CTAs/SM)
    int proj_smem = 2 * NSTAGE * STG_H * (int)sizeof(__half);  // 81920 B
    cudaFuncSetAttribute(proj_kernel, cudaFuncAttributeMaxDynamicSharedMemorySize, proj_smem);
    proj_kernel<<<576, 256, proj_smem>>>();

    prep_kernel<<<NT, 18 * 32>>>(qx_scale, qa_scale, kx_scale, ka_scale);

    int smem_bytes = 4 * TILE_H * (int)sizeof(__half);  // 69632 B
    cudaFuncSetAttribute(attn_mma_kernel, cudaFuncAttributeMaxDynamicSharedMemorySize, smem_bytes);
    attn_mma_kernel<<<dim3(NN / 128, HEADS, BB), 256, smem_bytes>>>(out);
}